// round 12
// baseline (speedup 1.0000x reference)
#include <cuda_runtime.h>
#include <cstddef>

#define BATCH 16
#define NPTS  1024
#define KNN   20
#define BN    (BATCH*NPTS)

typedef unsigned long long ull;

// ---------------- scratch (static device globals; allocation-free) ----------------
__device__ float g_hA[BN*256];
__device__ float g_hB[BN*256];
__device__ float g_u [BN*256];
__device__ float g_w [BN*256];
__device__ float g_ymax[BN*256];
__device__ float g_ymin[BN*256];
__device__ float g_xx[BN];
__device__ float g_dist[BATCH*NPTS*NPTS];       // 67 MB, L2-resident
__device__ float g_nodemin[BN*128];             // per-row mins of 8-col groups
__device__ int   g_idx[BN*KNN];
__device__ float g_ps[524288];                  // stats partials [o][P]
__device__ float g_pq[524288];
__device__ float g_scale[256];
__device__ float g_shift[256];
__device__ float g_part[BATCH*16*256];

// ---------------- f32x2 helpers ----------------
__device__ __forceinline__ void fma2(ull& d, ull a, ull b) {
    asm("fma.rn.f32x2 %0, %1, %2, %0;" : "+l"(d) : "l"(a), "l"(b));
}
__device__ __forceinline__ float2 upk(ull v) {
    float2 f; asm("mov.b64 {%0,%1}, %2;" : "=f"(f.x), "=f"(f.y) : "l"(v)); return f;
}
// duplicate a float into both lanes of an f32x2 register pair (ALU-pipe movs)
__device__ __forceinline__ ull dup2(float f) {
    ull r; asm("mov.b64 %0, {%1, %1};" : "=l"(r) : "f"(f)); return r;
}
__device__ __forceinline__ unsigned redux_min_u32(unsigned v) {
    unsigned r; asm("redux.sync.min.u32 %0, %1, 0xffffffff;" : "=r"(r) : "r"(v)); return r;
}
__device__ __forceinline__ int redux_min_s32(int v) {
    int r; asm("redux.sync.min.s32 %0, %1, 0xffffffff;" : "=r"(r) : "r"(v)); return r;
}
// Kahan compensated add: s += v with compensation c (4 FADD)
__device__ __forceinline__ void kadd(float& s, float& c, float v) {
    float y = v - c;
    float t = s + y;
    c = (t - s) - y;
    s = t;
}

// ---------------- prep: x (B,1,4,N) -> h (B,N,4) ----------------
__global__ void prep_kernel(const float* __restrict__ x, float* __restrict__ h) {
    int i = blockIdx.x*256 + threadIdx.x;          // over B*N*4
    int c = i & 3, n = (i >> 2) & (NPTS-1), b = i >> 12;
    h[i] = x[((size_t)b*4 + c)*NPTS + n];
}

// ---------------- xx[b,n] = |h_bn|^2 ----------------
template<int C>
__global__ void xx_kernel(const float* __restrict__ h, float* __restrict__ xx) {
    int i = blockIdx.x*256 + threadIdx.x;          // over B*N
    const float4* hp = (const float4*)(h + (size_t)i*C);
    float s = 0.f;
#pragma unroll
    for (int c = 0; c < C/4; c++) { float4 v = hp[c]; s += v.x*v.x + v.y*v.y + v.z*v.z + v.w*v.w; }
    xx[i] = s;
}

// ---------------- pairwise squared distances + per-group node mins ----------------
template<int C>
__global__ __launch_bounds__(256) void dist_kernel(const float* __restrict__ h,
                                                   const float* __restrict__ xx,
                                                   float* __restrict__ dist,
                                                   float* __restrict__ nodemin) {
    constexpr int KC = (C >= 8) ? 8 : 4;
    __shared__ float As[KC][136];   // 128 rows natural + pad
    __shared__ float Bs[KC][136];
    __shared__ float Ts[64][66];    // transpose staging (float2-aligned dump)
    int bx = blockIdx.x, by = blockIdx.y, b = blockIdx.z;
    if (bx > by) return;            // symmetry: compute lower triangle, mirror
    int n0 = by * 128, m0 = bx * 128;
    int tid = threadIdx.x;
    int tx = tid & 15, ty = tid >> 4;   // 16x16 threads, 8x8 values each
    ull acc[8][4];
#pragma unroll
    for (int i = 0; i < 8; i++)
#pragma unroll
        for (int j = 0; j < 4; j++) acc[i][j] = 0ull;
    const float* hb = h + (size_t)b*NPTS*C;
    for (int kk = 0; kk < C; kk += KC) {
        for (int e = tid; e < 128*KC; e += 256) {
            int r = e / KC, c = e % KC;
            As[c][r] = hb[(size_t)(n0 + r)*C + kk + c];
            Bs[c][r] = hb[(size_t)(m0 + r)*C + kk + c];
        }
        __syncthreads();
#pragma unroll
        for (int c = 0; c < KC; c++) {
            float4 a0 = *(const float4*)&As[c][ty*8];      // broadcast within warp
            float4 a1 = *(const float4*)&As[c][ty*8+4];
            ull A[8];
            A[0] = dup2(a0.x); A[1] = dup2(a0.y); A[2] = dup2(a0.z); A[3] = dup2(a0.w);
            A[4] = dup2(a1.x); A[5] = dup2(a1.y); A[6] = dup2(a1.z); A[7] = dup2(a1.w);
            const ull* bp = (const ull*)&Bs[c][tx*8];
            ull B[4];
#pragma unroll
            for (int j = 0; j < 4; j++) B[j] = bp[j];
#pragma unroll
            for (int i = 0; i < 8; i++)
#pragma unroll
                for (int j = 0; j < 4; j++) fma2(acc[i][j], A[i], B[j]);
        }
        __syncthreads();
    }
    const float* xxb = xx + b*NPTS;
    float xn[8], xm[8];
#pragma unroll
    for (int i = 0; i < 8; i++) { xn[i] = xxb[n0+ty*8+i]; xm[i] = xxb[m0+tx*8+i]; }
    float ov[8][8];
#pragma unroll
    for (int i = 0; i < 8; i++)
#pragma unroll
        for (int j = 0; j < 4; j++) {
            float2 p = upk(acc[i][j]);
            ov[i][2*j]   = xn[i] + xm[2*j]   - 2.f*p.x;
            ov[i][2*j+1] = xn[i] + xm[2*j+1] - 2.f*p.y;
        }
    float* db = dist + (size_t)b*NPTS*NPTS;
    float* nmb = nodemin + (size_t)b*NPTS*128;
#pragma unroll
    for (int i = 0; i < 8; i++) {
        size_t off = (size_t)(n0+ty*8+i)*NPTS + m0 + tx*8;
        *(float4*)&db[off]   = make_float4(ov[i][0], ov[i][1], ov[i][2], ov[i][3]);
        *(float4*)&db[off+4] = make_float4(ov[i][4], ov[i][5], ov[i][6], ov[i][7]);
        float m = fminf(fminf(fminf(ov[i][0],ov[i][1]), fminf(ov[i][2],ov[i][3])),
                        fminf(fminf(ov[i][4],ov[i][5]), fminf(ov[i][6],ov[i][7])));
        nmb[(size_t)(n0+ty*8+i)*128 + bx*16 + tx] = m;
    }
    if (bx == by) return;
#pragma unroll
    for (int j = 0; j < 8; j++) {
        float m = fminf(fminf(fminf(ov[0][j],ov[1][j]), fminf(ov[2][j],ov[3][j])),
                        fminf(fminf(ov[4][j],ov[5][j]), fminf(ov[6][j],ov[7][j])));
        nmb[(size_t)(m0+tx*8+j)*128 + by*16 + ty] = m;
    }
#pragma unroll
    for (int sr = 0; sr < 2; sr++)
#pragma unroll
        for (int sc = 0; sc < 2; sc++) {
            __syncthreads();
            if ((ty >> 3) == sr && (tx >> 3) == sc) {
#pragma unroll
                for (int i = 0; i < 8; i++)
#pragma unroll
                    for (int j = 0; j < 8; j++)
                        Ts[(tx & 7)*8 + j][(ty & 7)*8 + i] = ov[i][j];
            }
            __syncthreads();
            for (int e = tid; e < 64*32; e += 256) {
                int r = e >> 5, c2 = (e & 31) * 2;
                float2 v = *(float2*)&Ts[r][c2];
                *(float2*)&db[(size_t)(m0 + sc*64 + r)*NPTS + n0 + sr*64 + c2] = v;
            }
        }
}

// ---------------- top-k=20: candidate-pruned tournament, warp per row, NO smem ----------------
__global__ __launch_bounds__(256) void topk_kernel(const float* __restrict__ dist,
                                                   const float* __restrict__ nodemin,
                                                   int* __restrict__ idx) {
    int tid = threadIdx.x;
    int warp = tid >> 5, lane = tid & 31;
    int b = blockIdx.y;
    int n = blockIdx.x * 8 + warp;
    float4 t = *(const float4*)(nodemin + ((size_t)b*NPTS + n)*128 + lane*4);
    float nm[4] = {t.x, t.y, t.z, t.w};
    int mygrp = 0;
    // Phase A: 20 smallest groups by (nodemin, group index)
    for (int kk = 0; kk < KNN; kk++) {
        float lm = fminf(fminf(nm[0], nm[1]), fminf(nm[2], nm[3]));
        unsigned bu = __float_as_uint(lm);
        unsigned tu = bu ^ (((unsigned)((int)bu >> 31)) | 0x80000000u);
        unsigned gm = redux_min_u32(tu);
        int mygid = 0x7FFFFFFF;
        int g = 0;
        if (tu == gm) {
            g = (nm[0]==lm) ? 0 : (nm[1]==lm) ? 1 : (nm[2]==lm) ? 2 : 3;
            mygid = lane*4 + g;
        }
        int win = redux_min_s32(mygid);
        if (mygid == win) {
#pragma unroll
            for (int g2 = 0; g2 < 4; g2++) if (g2 == g) nm[g2] = 3.4e38f;
        }
        if (lane == kk) mygrp = win;
    }
    // Phase B: gather candidate leaves (one parallel LDG round, L2-resident)
    float v[8];
    int base;
    if (lane < KNN) {
        base = mygrp * 8;
        const float4* p = (const float4*)(dist + ((size_t)b*NPTS + n)*NPTS + base);
        float4 a = p[0], c = p[1];
        v[0]=a.x; v[1]=a.y; v[2]=a.z; v[3]=a.w;
        v[4]=c.x; v[5]=c.y; v[6]=c.z; v[7]=c.w;
    } else {
#pragma unroll
        for (int i = 0; i < 8; i++) v[i] = 3.4e38f;
        base = 0x3FFFFF00;
    }
    int* out = idx + ((size_t)b*NPTS + n)*KNN;
    // Phase C: exact top-20 over the candidate leaves
    for (int kk = 0; kk < KNN; kk++) {
        float lm = fminf(fminf(fminf(v[0],v[1]), fminf(v[2],v[3])),
                         fminf(fminf(v[4],v[5]), fminf(v[6],v[7])));
        unsigned bu = __float_as_uint(lm);
        unsigned tu = bu ^ (((unsigned)((int)bu >> 31)) | 0x80000000u);
        unsigned gm = redux_min_u32(tu);
        int mym = 0x7FFFFFFF;
        int li = 0;
        if (tu == gm) {
            li = 7;
#pragma unroll
            for (int i = 6; i >= 0; i--) if (v[i] == lm) li = i;
            mym = base + li;
        }
        int win = redux_min_s32(mym);
        if (mym == win) {
#pragma unroll
            for (int i = 0; i < 8; i++) if (i == li) v[i] = 3.4e38f;
        }
        if (lane == 0) out[kk] = win;
    }
}

// ---------------- u = h W1^T, w = h (W2-W1)^T : 128x64 tile, natural A + reg dup ----------------
template<int C, int O>
__global__ __launch_bounds__(256) void gemm_kernel(const float* __restrict__ h,
                                                   const float* __restrict__ W,
                                                   float* __restrict__ u,
                                                   float* __restrict__ w) {
    constexpr int KC = (C >= 8) ? 8 : 4;
    __shared__ float As[KC][136];
    __shared__ float B1[KC][72];
    __shared__ float B2[KC][72];
    int o0 = blockIdx.x * 64;
    int r0 = blockIdx.y * 128;
    int tid = threadIdx.x, tx = tid & 15, ty = tid >> 4;
    ull au[8][2], aw[8][2];
#pragma unroll
    for (int i = 0; i < 8; i++) { au[i][0]=0ull; au[i][1]=0ull; aw[i][0]=0ull; aw[i][1]=0ull; }
    for (int kk = 0; kk < C; kk += KC) {
        for (int e = tid; e < 128*KC; e += 256) {
            int r = e / KC, c = e % KC;
            As[c][r] = h[(size_t)(r0 + r)*C + kk + c];
        }
        for (int e = tid; e < 64*KC; e += 256) {
            int r = e / KC, c = e % KC;
            float w1 = W[(size_t)(o0 + r)*(2*C) + kk + c];
            float w2 = W[(size_t)(o0 + r)*(2*C) + C + kk + c];
            B1[c][r] = w1;
            B2[c][r] = w2 - w1;
        }
        __syncthreads();
#pragma unroll
        for (int c = 0; c < KC; c++) {
            float4 a0 = *(const float4*)&As[c][ty*8];
            float4 a1 = *(const float4*)&As[c][ty*8+4];
            ull A[8];
            A[0] = dup2(a0.x); A[1] = dup2(a0.y); A[2] = dup2(a0.z); A[3] = dup2(a0.w);
            A[4] = dup2(a1.x); A[5] = dup2(a1.y); A[6] = dup2(a1.z); A[7] = dup2(a1.w);
            ull p0 = *(const ull*)&B1[c][tx*4];
            ull p1 = *(const ull*)&B1[c][tx*4+2];
            ull q0 = *(const ull*)&B2[c][tx*4];
            ull q1 = *(const ull*)&B2[c][tx*4+2];
#pragma unroll
            for (int i = 0; i < 8; i++) {
                fma2(au[i][0], A[i], p0); fma2(au[i][1], A[i], p1);
                fma2(aw[i][0], A[i], q0); fma2(aw[i][1], A[i], q1);
            }
        }
        __syncthreads();
    }
#pragma unroll
    for (int i = 0; i < 8; i++) {
        float2 u0 = upk(au[i][0]), u1 = upk(au[i][1]);
        float2 v0 = upk(aw[i][0]), v1 = upk(aw[i][1]);
        size_t off = (size_t)(r0 + ty*8 + i)*O + o0 + tx*4;
        *(float4*)&u[off] = make_float4(u0.x, u0.y, u1.x, u1.y);
        *(float4*)&w[off] = make_float4(v0.x, v0.y, v1.x, v1.y);
    }
}

// ---------------- gather pass: u column-tile staged in SMEM, gathers from smem ----------------
// Block = (batch b, channel tile of T). u[b,:,tile] staged once (16-32 KB), then
// all 1024 nodes x KNN gathers hit smem instead of L2: u L2 traffic drops 20x.
// Per-node fp32 sums + Kahan cross-node; partials reduced in double by bnstats.
template<int O, int T>
__global__ __launch_bounds__(256) void stats_kernel(const float* __restrict__ u,
                                                    const float* __restrict__ w,
                                                    const int* __restrict__ idx,
                                                    float* __restrict__ ps, float* __restrict__ pq,
                                                    float* __restrict__ ymax, float* __restrict__ ymin) {
    constexpr int NCH4 = T/4;                 // float4 channel-groups per tile
    constexpr int NL   = 256/NCH4;            // node lanes
    constexpr int NPT  = NPTS/NL;             // nodes per thread
    constexpr int P    = BATCH*NL;            // partial columns per channel
    __shared__ float4 us[NPTS*NCH4];
    int ctile = blockIdx.x, b = blockIdx.y;
    int tid = threadIdx.x;
    int c4 = tid % NCH4, nl = tid / NCH4;
    // stage u column tile for this batch
    const float* ub = u + (size_t)b*NPTS*O + ctile*T;
    for (int e = tid; e < NPTS*NCH4; e += 256) {
        int r = e / NCH4, cc = e % NCH4;
        us[e] = *(const float4*)(ub + (size_t)r*O + cc*4);
    }
    __syncthreads();
    int obase = ctile*T + c4*4;
    float S0=0.f,S1=0.f,S2=0.f,S3=0.f,Q0=0.f,Q1=0.f,Q2=0.f,Q3=0.f;
    float cs0=0.f,cs1=0.f,cs2=0.f,cs3=0.f,cq0=0.f,cq1=0.f,cq2=0.f,cq3=0.f;
#pragma unroll
    for (int j = 0; j < NPT; j++) {
        int n = nl + j*NL;
        int gn = b*NPTS + n;
        float4 wv = *(const float4*)(w + (size_t)gn*O + obase);
        const int* ip = idx + (size_t)gn*KNN;
        float4 mx = make_float4(-3.4e38f,-3.4e38f,-3.4e38f,-3.4e38f);
        float4 mn = make_float4( 3.4e38f, 3.4e38f, 3.4e38f, 3.4e38f);
        float s0=0.f,s1=0.f,s2=0.f,s3=0.f,q0=0.f,q1=0.f,q2=0.f,q3=0.f;
#pragma unroll
        for (int k = 0; k < KNN; k++) {
            int r = ip[k];
            float4 y = us[r*NCH4 + c4];
            y.x += wv.x; y.y += wv.y; y.z += wv.z; y.w += wv.w;
            s0 += y.x; q0 += y.x*y.x; mx.x = fmaxf(mx.x,y.x); mn.x = fminf(mn.x,y.x);
            s1 += y.y; q1 += y.y*y.y; mx.y = fmaxf(mx.y,y.y); mn.y = fminf(mn.y,y.y);
            s2 += y.z; q2 += y.z*y.z; mx.z = fmaxf(mx.z,y.z); mn.z = fminf(mn.z,y.z);
            s3 += y.w; q3 += y.w*y.w; mx.w = fmaxf(mx.w,y.w); mn.w = fminf(mn.w,y.w);
        }
        *(float4*)(ymax + (size_t)gn*O + obase) = mx;
        *(float4*)(ymin + (size_t)gn*O + obase) = mn;
        kadd(S0, cs0, s0); kadd(Q0, cq0, q0);
        kadd(S1, cs1, s1); kadd(Q1, cq1, q1);
        kadd(S2, cs2, s2); kadd(Q2, cq2, q2);
        kadd(S3, cs3, s3); kadd(Q3, cq3, q3);
    }
    int col = b*NL + nl;
    ps[(size_t)(obase+0)*P + col] = S0 - cs0;  pq[(size_t)(obase+0)*P + col] = Q0 - cq0;
    ps[(size_t)(obase+1)*P + col] = S1 - cs1;  pq[(size_t)(obase+1)*P + col] = Q1 - cq1;
    ps[(size_t)(obase+2)*P + col] = S2 - cs2;  pq[(size_t)(obase+2)*P + col] = Q2 - cq2;
    ps[(size_t)(obase+3)*P + col] = S3 - cs3;  pq[(size_t)(obase+3)*P + col] = Q3 - cq3;
}

// ---------------- reduce fp32 partials in double -> scale/shift per channel ----------------
__global__ __launch_bounds__(128) void bnstats_kernel(const float* __restrict__ ps,
                                                      const float* __restrict__ pq,
                                                      const float* __restrict__ g,
                                                      const float* __restrict__ bt,
                                                      float* __restrict__ scale,
                                                      float* __restrict__ shift, int P) {
    __shared__ double shs[4], shq[4];
    int o = blockIdx.x;
    int tid = threadIdx.x, lane = tid & 31, wp = tid >> 5;
    double s = 0., q = 0.;
    for (int p = tid; p < P; p += 128) {
        s += (double)ps[(size_t)o*P + p];
        q += (double)pq[(size_t)o*P + p];
    }
#pragma unroll
    for (int off = 16; off; off >>= 1) {
        s += __shfl_down_sync(0xffffffffu, s, off);
        q += __shfl_down_sync(0xffffffffu, q, off);
    }
    if (lane == 0) { shs[wp] = s; shq[wp] = q; }
    __syncthreads();
    if (tid == 0) {
        s = shs[0] + shs[1] + shs[2] + shs[3];
        q = shq[0] + shq[1] + shq[2] + shq[3];
        const double inv = 1.0 / (double)(BATCH*NPTS*KNN);
        double mean = s * inv;
        double var  = q * inv - mean*mean;
        double rs   = 1.0 / sqrt(var + 1e-5);
        double sc   = (double)g[o] * rs;
        scale[o] = (float)sc;
        shift[o] = (float)((double)bt[o] - mean*sc);
    }
}

// ---------------- finalize: BN + LeakyReLU on the k-extremum (monotone trick) ----------------
template<int O>
__global__ void finalize_kernel(const float4* __restrict__ ymax, const float4* __restrict__ ymin,
                                const float4* __restrict__ scale, const float4* __restrict__ shift,
                                float4* __restrict__ hout) {
    int i = blockIdx.x*256 + threadIdx.x;           // over BN*O/4
    int o4 = i & (O/4 - 1);
    float4 sc = scale[o4], sh = shift[o4];
    float4 mx = ymax[i], mn = ymin[i];
    float4 r;
    float v;
    v = (sc.x >= 0.f ? mx.x : mn.x)*sc.x + sh.x; r.x = (v >= 0.f) ? v : 0.2f*v;
    v = (sc.y >= 0.f ? mx.y : mn.y)*sc.y + sh.y; r.y = (v >= 0.f) ? v : 0.2f*v;
    v = (sc.z >= 0.f ? mx.z : mn.z)*sc.z + sh.z; r.z = (v >= 0.f) ? v : 0.2f*v;
    v = (sc.w >= 0.f ? mx.w : mn.w)*sc.w + sh.w; r.w = (v >= 0.f) ? v : 0.2f*v;
    hout[i] = r;
}

// ---------------- final max over N (two deterministic stages) ----------------
__global__ void pmax_kernel(const float* __restrict__ h, float* __restrict__ part) {
    int b = blockIdx.y, ch = blockIdx.x, o = threadIdx.x;
    const float* hp = h + ((size_t)b*NPTS + ch*64)*256 + o;
    float m = -3.4e38f;
    for (int n = 0; n < 64; n++) m = fmaxf(m, hp[(size_t)n*256]);
    part[((size_t)b*16 + ch)*256 + o] = m;
}
__global__ void fmax_kernel(const float* __restrict__ part, float* __restrict__ out) {
    int b = blockIdx.x, o = threadIdx.x;
    float m = -3.4e38f;
    for (int c = 0; c < 16; c++) m = fmaxf(m, part[((size_t)b*16 + c)*256 + o]);
    out[(size_t)b*256 + o] = m;
}

// ---------------- host orchestration ----------------
struct Scratch {
    float *hA, *hB, *u, *w, *ymax, *ymin, *xx, *dist, *nodemin, *ps, *pq, *scale, *shift, *part;
    int* idx;
};

template<int C, int O>
static void run_layer(const float* hin, float* hout, const float* W,
                      const float* g, const float* bt, const Scratch& Z) {
    constexpr int T = (O == 64) ? 4 : 8;           // channel tile for stats
    constexpr int P = BATCH * (256/(T/4));         // partial columns per channel
    xx_kernel<C><<<BN/256, 256>>>(hin, Z.xx);
    dist_kernel<C><<<dim3(8, 8, BATCH), 256>>>(hin, Z.xx, Z.dist, Z.nodemin);
    topk_kernel<<<dim3(NPTS/8, BATCH), 256>>>(Z.dist, Z.nodemin, Z.idx);
    gemm_kernel<C, O><<<dim3(O/64, BN/128), 256>>>(hin, W, Z.u, Z.w);
    stats_kernel<O, T><<<dim3(O/T, BATCH), 256>>>(Z.u, Z.w, Z.idx, Z.ps, Z.pq, Z.ymax, Z.ymin);
    bnstats_kernel<<<O, 128>>>(Z.ps, Z.pq, g, bt, Z.scale, Z.shift, P);
    finalize_kernel<O><<<(BN*O/4)/256, 256>>>((const float4*)Z.ymax, (const float4*)Z.ymin,
                                              (const float4*)Z.scale, (const float4*)Z.shift,
                                              (float4*)hout);
}

extern "C" void kernel_launch(void* const* d_in, const int* in_sizes, int n_in,
                              void* d_out, int out_size) {
    const float* x = (const float*)d_in[0];
    const float* Wp[4]; const float* gp[4]; const float* bp[4];
    for (int i = 0; i < 4; i++) {
        Wp[i] = (const float*)d_in[1 + 3*i];
        gp[i] = (const float*)d_in[2 + 3*i];
        bp[i] = (const float*)d_in[3 + 3*i];
    }
    Scratch Z;
    cudaGetSymbolAddress((void**)&Z.hA,      g_hA);
    cudaGetSymbolAddress((void**)&Z.hB,      g_hB);
    cudaGetSymbolAddress((void**)&Z.u,       g_u);
    cudaGetSymbolAddress((void**)&Z.w,       g_w);
    cudaGetSymbolAddress((void**)&Z.ymax,    g_ymax);
    cudaGetSymbolAddress((void**)&Z.ymin,    g_ymin);
    cudaGetSymbolAddress((void**)&Z.xx,      g_xx);
    cudaGetSymbolAddress((void**)&Z.dist,    g_dist);
    cudaGetSymbolAddress((void**)&Z.nodemin, g_nodemin);
    cudaGetSymbolAddress((void**)&Z.ps,      g_ps);
    cudaGetSymbolAddress((void**)&Z.pq,      g_pq);
    cudaGetSymbolAddress((void**)&Z.scale,   g_scale);
    cudaGetSymbolAddress((void**)&Z.shift,   g_shift);
    cudaGetSymbolAddress((void**)&Z.part,    g_part);
    cudaGetSymbolAddress((void**)&Z.idx,     g_idx);

    prep_kernel<<<(BN*4)/256, 256>>>(x, Z.hA);

    run_layer<4,   64 >(Z.hA, Z.hB, Wp[0], gp[0], bp[0], Z);
    run_layer<64,  64 >(Z.hB, Z.hA, Wp[1], gp[1], bp[1], Z);
    run_layer<64,  128>(Z.hA, Z.hB, Wp[2], gp[2], bp[2], Z);
    run_layer<128, 256>(Z.hB, Z.hA, Wp[3], gp[3], bp[3], Z);

    pmax_kernel<<<dim3(16, BATCH), 256>>>(Z.hA, Z.part);
    fmax_kernel<<<BATCH, 256>>>(Z.part, (float*)d_out);
}

// round 13
// speedup vs baseline: 1.0729x; 1.0729x over previous
#include <cuda_runtime.h>
#include <cstddef>

#define BATCH 16
#define NPTS  1024
#define KNN   20
#define BN    (BATCH*NPTS)

typedef unsigned long long ull;

// ---------------- scratch (static device globals; allocation-free) ----------------
__device__ float g_hA[BN*256];
__device__ float g_hB[BN*256];
__device__ float g_u [BN*256];
__device__ float g_w [BN*256];
__device__ float g_ymax[BN*256];
__device__ float g_ymin[BN*256];
__device__ float g_xx[BN];
__device__ float g_dist[BATCH*NPTS*NPTS];       // 67 MB, L2-resident
__device__ float g_nodemin[BN*128];             // per-row mins of 8-col groups
__device__ int   g_idx[BN*KNN];
__device__ float g_ps[262144];                  // stats partials [o][P], O*P == 262144
__device__ float g_pq[262144];
__device__ float g_scale[256];
__device__ float g_shift[256];
__device__ float g_part[BATCH*16*256];

// ---------------- f32x2 helpers ----------------
__device__ __forceinline__ void fma2(ull& d, ull a, ull b) {
    asm("fma.rn.f32x2 %0, %1, %2, %0;" : "+l"(d) : "l"(a), "l"(b));
}
__device__ __forceinline__ float2 upk(ull v) {
    float2 f; asm("mov.b64 {%0,%1}, %2;" : "=f"(f.x), "=f"(f.y) : "l"(v)); return f;
}
// duplicate a float into both lanes of an f32x2 register pair (ALU-pipe movs)
__device__ __forceinline__ ull dup2(float f) {
    ull r; asm("mov.b64 %0, {%1, %1};" : "=l"(r) : "f"(f)); return r;
}
__device__ __forceinline__ unsigned redux_min_u32(unsigned v) {
    unsigned r; asm("redux.sync.min.u32 %0, %1, 0xffffffff;" : "=r"(r) : "r"(v)); return r;
}
__device__ __forceinline__ int redux_min_s32(int v) {
    int r; asm("redux.sync.min.s32 %0, %1, 0xffffffff;" : "=r"(r) : "r"(v)); return r;
}
// Kahan compensated add: s += v with compensation c (4 FADD)
__device__ __forceinline__ void kadd(float& s, float& c, float v) {
    float y = v - c;
    float t = s + y;
    c = (t - s) - y;
    s = t;
}

// ---------------- prep: x (B,1,4,N) -> h (B,N,4) ----------------
__global__ void prep_kernel(const float* __restrict__ x, float* __restrict__ h) {
    int i = blockIdx.x*256 + threadIdx.x;          // over B*N*4
    int c = i & 3, n = (i >> 2) & (NPTS-1), b = i >> 12;
    h[i] = x[((size_t)b*4 + c)*NPTS + n];
}

// ---------------- xx[b,n] = |h_bn|^2 ----------------
template<int C>
__global__ void xx_kernel(const float* __restrict__ h, float* __restrict__ xx) {
    int i = blockIdx.x*256 + threadIdx.x;          // over B*N
    const float4* hp = (const float4*)(h + (size_t)i*C);
    float s = 0.f;
#pragma unroll
    for (int c = 0; c < C/4; c++) { float4 v = hp[c]; s += v.x*v.x + v.y*v.y + v.z*v.z + v.w*v.w; }
    xx[i] = s;
}

// ---------------- pairwise squared distances + per-group node mins ----------------
template<int C>
__global__ __launch_bounds__(256) void dist_kernel(const float* __restrict__ h,
                                                   const float* __restrict__ xx,
                                                   float* __restrict__ dist,
                                                   float* __restrict__ nodemin) {
    constexpr int KC = (C >= 8) ? 8 : 4;
    __shared__ float As[KC][136];   // 128 rows natural + pad
    __shared__ float Bs[KC][136];
    __shared__ float Ts[64][66];    // transpose staging (float2-aligned dump)
    int bx = blockIdx.x, by = blockIdx.y, b = blockIdx.z;
    if (bx > by) return;            // symmetry: compute lower triangle, mirror
    int n0 = by * 128, m0 = bx * 128;
    int tid = threadIdx.x;
    int tx = tid & 15, ty = tid >> 4;   // 16x16 threads, 8x8 values each
    ull acc[8][4];
#pragma unroll
    for (int i = 0; i < 8; i++)
#pragma unroll
        for (int j = 0; j < 4; j++) acc[i][j] = 0ull;
    const float* hb = h + (size_t)b*NPTS*C;
    for (int kk = 0; kk < C; kk += KC) {
        for (int e = tid; e < 128*KC; e += 256) {
            int r = e / KC, c = e % KC;
            As[c][r] = hb[(size_t)(n0 + r)*C + kk + c];
            Bs[c][r] = hb[(size_t)(m0 + r)*C + kk + c];
        }
        __syncthreads();
#pragma unroll
        for (int c = 0; c < KC; c++) {
            float4 a0 = *(const float4*)&As[c][ty*8];      // broadcast within warp
            float4 a1 = *(const float4*)&As[c][ty*8+4];
            ull A[8];
            A[0] = dup2(a0.x); A[1] = dup2(a0.y); A[2] = dup2(a0.z); A[3] = dup2(a0.w);
            A[4] = dup2(a1.x); A[5] = dup2(a1.y); A[6] = dup2(a1.z); A[7] = dup2(a1.w);
            const ull* bp = (const ull*)&Bs[c][tx*8];
            ull B[4];
#pragma unroll
            for (int j = 0; j < 4; j++) B[j] = bp[j];
#pragma unroll
            for (int i = 0; i < 8; i++)
#pragma unroll
                for (int j = 0; j < 4; j++) fma2(acc[i][j], A[i], B[j]);
        }
        __syncthreads();
    }
    const float* xxb = xx + b*NPTS;
    float xn[8], xm[8];
#pragma unroll
    for (int i = 0; i < 8; i++) { xn[i] = xxb[n0+ty*8+i]; xm[i] = xxb[m0+tx*8+i]; }
    float ov[8][8];
#pragma unroll
    for (int i = 0; i < 8; i++)
#pragma unroll
        for (int j = 0; j < 4; j++) {
            float2 p = upk(acc[i][j]);
            ov[i][2*j]   = xn[i] + xm[2*j]   - 2.f*p.x;
            ov[i][2*j+1] = xn[i] + xm[2*j+1] - 2.f*p.y;
        }
    float* db = dist + (size_t)b*NPTS*NPTS;
    float* nmb = nodemin + (size_t)b*NPTS*128;
#pragma unroll
    for (int i = 0; i < 8; i++) {
        size_t off = (size_t)(n0+ty*8+i)*NPTS + m0 + tx*8;
        *(float4*)&db[off]   = make_float4(ov[i][0], ov[i][1], ov[i][2], ov[i][3]);
        *(float4*)&db[off+4] = make_float4(ov[i][4], ov[i][5], ov[i][6], ov[i][7]);
        float m = fminf(fminf(fminf(ov[i][0],ov[i][1]), fminf(ov[i][2],ov[i][3])),
                        fminf(fminf(ov[i][4],ov[i][5]), fminf(ov[i][6],ov[i][7])));
        nmb[(size_t)(n0+ty*8+i)*128 + bx*16 + tx] = m;
    }
    if (bx == by) return;
#pragma unroll
    for (int j = 0; j < 8; j++) {
        float m = fminf(fminf(fminf(ov[0][j],ov[1][j]), fminf(ov[2][j],ov[3][j])),
                        fminf(fminf(ov[4][j],ov[5][j]), fminf(ov[6][j],ov[7][j])));
        nmb[(size_t)(m0+tx*8+j)*128 + by*16 + ty] = m;
    }
#pragma unroll
    for (int sr = 0; sr < 2; sr++)
#pragma unroll
        for (int sc = 0; sc < 2; sc++) {
            __syncthreads();
            if ((ty >> 3) == sr && (tx >> 3) == sc) {
#pragma unroll
                for (int i = 0; i < 8; i++)
#pragma unroll
                    for (int j = 0; j < 8; j++)
                        Ts[(tx & 7)*8 + j][(ty & 7)*8 + i] = ov[i][j];
            }
            __syncthreads();
            for (int e = tid; e < 64*32; e += 256) {
                int r = e >> 5, c2 = (e & 31) * 2;
                float2 v = *(float2*)&Ts[r][c2];
                *(float2*)&db[(size_t)(m0 + sc*64 + r)*NPTS + n0 + sr*64 + c2] = v;
            }
        }
}

// ---------------- top-k=20: candidate-pruned tournament, warp per row, NO smem ----------------
__global__ __launch_bounds__(256) void topk_kernel(const float* __restrict__ dist,
                                                   const float* __restrict__ nodemin,
                                                   int* __restrict__ idx) {
    int tid = threadIdx.x;
    int warp = tid >> 5, lane = tid & 31;
    int b = blockIdx.y;
    int n = blockIdx.x * 8 + warp;
    float4 t = *(const float4*)(nodemin + ((size_t)b*NPTS + n)*128 + lane*4);
    float nm[4] = {t.x, t.y, t.z, t.w};
    int mygrp = 0;
    // Phase A: 20 smallest groups by (nodemin, group index)
    for (int kk = 0; kk < KNN; kk++) {
        float lm = fminf(fminf(nm[0], nm[1]), fminf(nm[2], nm[3]));
        unsigned bu = __float_as_uint(lm);
        unsigned tu = bu ^ (((unsigned)((int)bu >> 31)) | 0x80000000u);
        unsigned gm = redux_min_u32(tu);
        int mygid = 0x7FFFFFFF;
        int g = 0;
        if (tu == gm) {
            g = (nm[0]==lm) ? 0 : (nm[1]==lm) ? 1 : (nm[2]==lm) ? 2 : 3;
            mygid = lane*4 + g;
        }
        int win = redux_min_s32(mygid);
        if (mygid == win) {
#pragma unroll
            for (int g2 = 0; g2 < 4; g2++) if (g2 == g) nm[g2] = 3.4e38f;
        }
        if (lane == kk) mygrp = win;
    }
    // Phase B: gather candidate leaves (one parallel LDG round, L2-resident)
    float v[8];
    int base;
    if (lane < KNN) {
        base = mygrp * 8;
        const float4* p = (const float4*)(dist + ((size_t)b*NPTS + n)*NPTS + base);
        float4 a = p[0], c = p[1];
        v[0]=a.x; v[1]=a.y; v[2]=a.z; v[3]=a.w;
        v[4]=c.x; v[5]=c.y; v[6]=c.z; v[7]=c.w;
    } else {
#pragma unroll
        for (int i = 0; i < 8; i++) v[i] = 3.4e38f;
        base = 0x3FFFFF00;
    }
    int* out = idx + ((size_t)b*NPTS + n)*KNN;
    // Phase C: exact top-20 over the candidate leaves
    for (int kk = 0; kk < KNN; kk++) {
        float lm = fminf(fminf(fminf(v[0],v[1]), fminf(v[2],v[3])),
                         fminf(fminf(v[4],v[5]), fminf(v[6],v[7])));
        unsigned bu = __float_as_uint(lm);
        unsigned tu = bu ^ (((unsigned)((int)bu >> 31)) | 0x80000000u);
        unsigned gm = redux_min_u32(tu);
        int mym = 0x7FFFFFFF;
        int li = 0;
        if (tu == gm) {
            li = 7;
#pragma unroll
            for (int i = 6; i >= 0; i--) if (v[i] == lm) li = i;
            mym = base + li;
        }
        int win = redux_min_s32(mym);
        if (mym == win) {
#pragma unroll
            for (int i = 0; i < 8; i++) if (i == li) v[i] = 3.4e38f;
        }
        if (lane == 0) out[kk] = win;
    }
}

// ---------------- u = h W1^T, w = h (W2-W1)^T : 128x64 tile, natural A + reg dup ----------------
template<int C, int O>
__global__ __launch_bounds__(256) void gemm_kernel(const float* __restrict__ h,
                                                   const float* __restrict__ W,
                                                   float* __restrict__ u,
                                                   float* __restrict__ w) {
    constexpr int KC = (C >= 8) ? 8 : 4;
    __shared__ float As[KC][136];
    __shared__ float B1[KC][72];
    __shared__ float B2[KC][72];
    int o0 = blockIdx.x * 64;
    int r0 = blockIdx.y * 128;
    int tid = threadIdx.x, tx = tid & 15, ty = tid >> 4;
    ull au[8][2], aw[8][2];
#pragma unroll
    for (int i = 0; i < 8; i++) { au[i][0]=0ull; au[i][1]=0ull; aw[i][0]=0ull; aw[i][1]=0ull; }
    for (int kk = 0; kk < C; kk += KC) {
        for (int e = tid; e < 128*KC; e += 256) {
            int r = e / KC, c = e % KC;
            As[c][r] = h[(size_t)(r0 + r)*C + kk + c];
        }
        for (int e = tid; e < 64*KC; e += 256) {
            int r = e / KC, c = e % KC;
            float w1 = W[(size_t)(o0 + r)*(2*C) + kk + c];
            float w2 = W[(size_t)(o0 + r)*(2*C) + C + kk + c];
            B1[c][r] = w1;
            B2[c][r] = w2 - w1;
        }
        __syncthreads();
#pragma unroll
        for (int c = 0; c < KC; c++) {
            float4 a0 = *(const float4*)&As[c][ty*8];
            float4 a1 = *(const float4*)&As[c][ty*8+4];
            ull A[8];
            A[0] = dup2(a0.x); A[1] = dup2(a0.y); A[2] = dup2(a0.z); A[3] = dup2(a0.w);
            A[4] = dup2(a1.x); A[5] = dup2(a1.y); A[6] = dup2(a1.z); A[7] = dup2(a1.w);
            ull p0 = *(const ull*)&B1[c][tx*4];
            ull p1 = *(const ull*)&B1[c][tx*4+2];
            ull q0 = *(const ull*)&B2[c][tx*4];
            ull q1 = *(const ull*)&B2[c][tx*4+2];
#pragma unroll
            for (int i = 0; i < 8; i++) {
                fma2(au[i][0], A[i], p0); fma2(au[i][1], A[i], p1);
                fma2(aw[i][0], A[i], q0); fma2(aw[i][1], A[i], q1);
            }
        }
        __syncthreads();
    }
#pragma unroll
    for (int i = 0; i < 8; i++) {
        float2 u0 = upk(au[i][0]), u1 = upk(au[i][1]);
        float2 v0 = upk(aw[i][0]), v1 = upk(aw[i][1]);
        size_t off = (size_t)(r0 + ty*8 + i)*O + o0 + tx*4;
        *(float4*)&u[off] = make_float4(u0.x, u0.y, u1.x, u1.y);
        *(float4*)&w[off] = make_float4(v0.x, v0.y, v1.x, v1.y);
    }
}

// ---------------- gather pass (R11 shape): float4 loads, fp32 node sums + Kahan ----------------
template<int O>
__global__ __launch_bounds__(256) void stats_kernel(const float* __restrict__ u,
                                                    const float* __restrict__ w,
                                                    const int* __restrict__ idx,
                                                    float* __restrict__ ps, float* __restrict__ pq,
                                                    float* __restrict__ ymax, float* __restrict__ ymin,
                                                    int P) {
    constexpr int C4 = O/4;            // channel groups of 4
    constexpr int NL = 256/C4;         // node lanes
    __shared__ int idxs[64*KNN];
    int blk = blockIdx.x, node0 = blk * 64;
    int tid = threadIdx.x;
    int c4 = tid % C4, nl = tid / C4;
    for (int e = tid; e < 64*KNN; e += 256) idxs[e] = idx[(size_t)node0*KNN + e];
    __syncthreads();
    const float4* ub = (const float4*)(u + (size_t)(node0 & ~(NPTS-1))*O);   // batch base
    float S0=0.f,S1=0.f,S2=0.f,S3=0.f,Q0=0.f,Q1=0.f,Q2=0.f,Q3=0.f;
    float cs0=0.f,cs1=0.f,cs2=0.f,cs3=0.f,cq0=0.f,cq1=0.f,cq2=0.f,cq3=0.f;
    for (int ni = nl; ni < 64; ni += NL) {
        int n = node0 + ni;
        float4 wv = *(const float4*)(w + (size_t)n*O + c4*4);
        float4 mx = make_float4(-3.4e38f,-3.4e38f,-3.4e38f,-3.4e38f);
        float4 mn = make_float4( 3.4e38f, 3.4e38f, 3.4e38f, 3.4e38f);
        float s0=0.f,s1=0.f,s2=0.f,s3=0.f,q0=0.f,q1=0.f,q2=0.f,q3=0.f;
#pragma unroll
        for (int k = 0; k < KNN; k++) {
            int r = idxs[ni*KNN + k];
            float4 y = ub[(size_t)r*C4 + c4];
            y.x += wv.x; y.y += wv.y; y.z += wv.z; y.w += wv.w;
            s0 += y.x; q0 += y.x*y.x; mx.x = fmaxf(mx.x,y.x); mn.x = fminf(mn.x,y.x);
            s1 += y.y; q1 += y.y*y.y; mx.y = fmaxf(mx.y,y.y); mn.y = fminf(mn.y,y.y);
            s2 += y.z; q2 += y.z*y.z; mx.z = fmaxf(mx.z,y.z); mn.z = fminf(mn.z,y.z);
            s3 += y.w; q3 += y.w*y.w; mx.w = fmaxf(mx.w,y.w); mn.w = fminf(mn.w,y.w);
        }
        *(float4*)(ymax + (size_t)n*O + c4*4) = mx;
        *(float4*)(ymin + (size_t)n*O + c4*4) = mn;
        kadd(S0, cs0, s0); kadd(Q0, cq0, q0);
        kadd(S1, cs1, s1); kadd(Q1, cq1, q1);
        kadd(S2, cs2, s2); kadd(Q2, cq2, q2);
        kadd(S3, cs3, s3); kadd(Q3, cq3, q3);
    }
    int col = blk*NL + nl;
    ps[(size_t)(c4*4+0)*P + col] = S0 - cs0;  pq[(size_t)(c4*4+0)*P + col] = Q0 - cq0;
    ps[(size_t)(c4*4+1)*P + col] = S1 - cs1;  pq[(size_t)(c4*4+1)*P + col] = Q1 - cq1;
    ps[(size_t)(c4*4+2)*P + col] = S2 - cs2;  pq[(size_t)(c4*4+2)*P + col] = Q2 - cq2;
    ps[(size_t)(c4*4+3)*P + col] = S3 - cs3;  pq[(size_t)(c4*4+3)*P + col] = Q3 - cq3;
}

// ---------------- reduce fp32 partials in double -> scale/shift per channel ----------------
__global__ __launch_bounds__(128) void bnstats_kernel(const float* __restrict__ ps,
                                                      const float* __restrict__ pq,
                                                      const float* __restrict__ g,
                                                      const float* __restrict__ bt,
                                                      float* __restrict__ scale,
                                                      float* __restrict__ shift, int P) {
    __shared__ double shs[4], shq[4];
    int o = blockIdx.x;
    int tid = threadIdx.x, lane = tid & 31, wp = tid >> 5;
    double s = 0., q = 0.;
    for (int p = tid; p < P; p += 128) {
        s += (double)ps[(size_t)o*P + p];
        q += (double)pq[(size_t)o*P + p];
    }
#pragma unroll
    for (int off = 16; off; off >>= 1) {
        s += __shfl_down_sync(0xffffffffu, s, off);
        q += __shfl_down_sync(0xffffffffu, q, off);
    }
    if (lane == 0) { shs[wp] = s; shq[wp] = q; }
    __syncthreads();
    if (tid == 0) {
        s = shs[0] + shs[1] + shs[2] + shs[3];
        q = shq[0] + shq[1] + shq[2] + shq[3];
        const double inv = 1.0 / (double)(BATCH*NPTS*KNN);
        double mean = s * inv;
        double var  = q * inv - mean*mean;
        double rs   = 1.0 / sqrt(var + 1e-5);
        double sc   = (double)g[o] * rs;
        scale[o] = (float)sc;
        shift[o] = (float)((double)bt[o] - mean*sc);
    }
}

// ---------------- finalize: BN + LeakyReLU on the k-extremum (monotone trick) ----------------
template<int O>
__global__ void finalize_kernel(const float4* __restrict__ ymax, const float4* __restrict__ ymin,
                                const float4* __restrict__ scale, const float4* __restrict__ shift,
                                float4* __restrict__ hout) {
    int i = blockIdx.x*256 + threadIdx.x;           // over BN*O/4
    int o4 = i & (O/4 - 1);
    float4 sc = scale[o4], sh = shift[o4];
    float4 mx = ymax[i], mn = ymin[i];
    float4 r;
    float v;
    v = (sc.x >= 0.f ? mx.x : mn.x)*sc.x + sh.x; r.x = (v >= 0.f) ? v : 0.2f*v;
    v = (sc.y >= 0.f ? mx.y : mn.y)*sc.y + sh.y; r.y = (v >= 0.f) ? v : 0.2f*v;
    v = (sc.z >= 0.f ? mx.z : mn.z)*sc.z + sh.z; r.z = (v >= 0.f) ? v : 0.2f*v;
    v = (sc.w >= 0.f ? mx.w : mn.w)*sc.w + sh.w; r.w = (v >= 0.f) ? v : 0.2f*v;
    hout[i] = r;
}

// ---------------- final max over N (two deterministic stages) ----------------
__global__ void pmax_kernel(const float* __restrict__ h, float* __restrict__ part) {
    int b = blockIdx.y, ch = blockIdx.x, o = threadIdx.x;
    const float* hp = h + ((size_t)b*NPTS + ch*64)*256 + o;
    float m = -3.4e38f;
    for (int n = 0; n < 64; n++) m = fmaxf(m, hp[(size_t)n*256]);
    part[((size_t)b*16 + ch)*256 + o] = m;
}
__global__ void fmax_kernel(const float* __restrict__ part, float* __restrict__ out) {
    int b = blockIdx.x, o = threadIdx.x;
    float m = -3.4e38f;
    for (int c = 0; c < 16; c++) m = fmaxf(m, part[((size_t)b*16 + c)*256 + o]);
    out[(size_t)b*256 + o] = m;
}

// ---------------- host orchestration ----------------
struct Scratch {
    float *hA, *hB, *u, *w, *ymax, *ymin, *xx, *dist, *nodemin, *ps, *pq, *scale, *shift, *part;
    int* idx;
};

// side stream + fork/join events for overlapping gemm with dist+topk
static cudaStream_t g_s2 = nullptr;
static cudaEvent_t  g_evF[4], g_evJ[4];

template<int C, int O>
static void run_layer(const float* hin, float* hout, const float* W,
                      const float* g, const float* bt, const Scratch& Z, int li) {
    int P = 262144 / O;
    // fork: gemm(hin, W) is independent of the xx->dist->topk chain
    cudaEventRecord(g_evF[li], 0);
    cudaStreamWaitEvent(g_s2, g_evF[li], 0);
    gemm_kernel<C, O><<<dim3(O/64, BN/128), 256, 0, g_s2>>>(hin, W, Z.u, Z.w);
    cudaEventRecord(g_evJ[li], g_s2);

    xx_kernel<C><<<BN/256, 256>>>(hin, Z.xx);
    dist_kernel<C><<<dim3(8, 8, BATCH), 256>>>(hin, Z.xx, Z.dist, Z.nodemin);
    topk_kernel<<<dim3(NPTS/8, BATCH), 256>>>(Z.dist, Z.nodemin, Z.idx);

    // join before the gather needs u/w
    cudaStreamWaitEvent(0, g_evJ[li], 0);
    stats_kernel<O><<<BN/64, 256>>>(Z.u, Z.w, Z.idx, Z.ps, Z.pq, Z.ymax, Z.ymin, P);
    bnstats_kernel<<<O, 128>>>(Z.ps, Z.pq, g, bt, Z.scale, Z.shift, P);
    finalize_kernel<O><<<(BN*O/4)/256, 256>>>((const float4*)Z.ymax, (const float4*)Z.ymin,
                                              (const float4*)Z.scale, (const float4*)Z.shift,
                                              (float4*)hout);
}

extern "C" void kernel_launch(void* const* d_in, const int* in_sizes, int n_in,
                              void* d_out, int out_size) {
    if (g_s2 == nullptr) {                          // one-time resource setup (first,
        cudaStreamCreateWithFlags(&g_s2, cudaStreamNonBlocking);   // uncaptured call)
        for (int i = 0; i < 4; i++) {
            cudaEventCreateWithFlags(&g_evF[i], cudaEventDisableTiming);
            cudaEventCreateWithFlags(&g_evJ[i], cudaEventDisableTiming);
        }
    }
    const float* x = (const float*)d_in[0];
    const float* Wp[4]; const float* gp[4]; const float* bp[4];
    for (int i = 0; i < 4; i++) {
        Wp[i] = (const float*)d_in[1 + 3*i];
        gp[i] = (const float*)d_in[2 + 3*i];
        bp[i] = (const float*)d_in[3 + 3*i];
    }
    Scratch Z;
    cudaGetSymbolAddress((void**)&Z.hA,      g_hA);
    cudaGetSymbolAddress((void**)&Z.hB,      g_hB);
    cudaGetSymbolAddress((void**)&Z.u,       g_u);
    cudaGetSymbolAddress((void**)&Z.w,       g_w);
    cudaGetSymbolAddress((void**)&Z.ymax,    g_ymax);
    cudaGetSymbolAddress((void**)&Z.ymin,    g_ymin);
    cudaGetSymbolAddress((void**)&Z.xx,      g_xx);
    cudaGetSymbolAddress((void**)&Z.dist,    g_dist);
    cudaGetSymbolAddress((void**)&Z.nodemin, g_nodemin);
    cudaGetSymbolAddress((void**)&Z.ps,      g_ps);
    cudaGetSymbolAddress((void**)&Z.pq,      g_pq);
    cudaGetSymbolAddress((void**)&Z.scale,   g_scale);
    cudaGetSymbolAddress((void**)&Z.shift,   g_shift);
    cudaGetSymbolAddress((void**)&Z.part,    g_part);
    cudaGetSymbolAddress((void**)&Z.idx,     g_idx);

    prep_kernel<<<(BN*4)/256, 256>>>(x, Z.hA);

    run_layer<4,   64 >(Z.hA, Z.hB, Wp[0], gp[0], bp[0], Z, 0);
    run_layer<64,  64 >(Z.hB, Z.hA, Wp[1], gp[1], bp[1], Z, 1);
    run_layer<64,  128>(Z.hA, Z.hB, Wp[2], gp[2], bp[2], Z, 2);
    run_layer<128, 256>(Z.hB, Z.hA, Wp[3], gp[3], bp[3], Z, 3);

    pmax_kernel<<<dim3(16, BATCH), 256>>>(Z.hA, Z.part);
    fmax_kernel<<<BATCH, 256>>>(Z.part, (float*)d_out);
}

// round 14
// speedup vs baseline: 1.0780x; 1.0048x over previous
#include <cuda_runtime.h>
#include <cstddef>

#define BATCH 16
#define NPTS  1024
#define KNN   20
#define BN    (BATCH*NPTS)

typedef unsigned long long ull;

// ---------------- scratch (static device globals; allocation-free) ----------------
__device__ float g_hA[BN*256];
__device__ float g_hB[BN*256];
__device__ float g_u [BN*256];
__device__ float g_w [BN*256];
__device__ float g_ymax[BN*256];
__device__ float g_ymin[BN*256];
__device__ float g_xx[BN];
__device__ float g_dist[BATCH*NPTS*NPTS];       // 67 MB, L2-resident
__device__ float g_nodemin[BN*128];             // per-row mins of 8-col groups
__device__ int   g_idx[BN*KNN];
__device__ float g_ps[262144];                  // stats partials [o][P], O*P == 262144
__device__ float g_pq[262144];
__device__ float g_scale[256];
__device__ float g_shift[256];
__device__ float g_part[BATCH*16*256];

// ---------------- f32x2 helpers ----------------
__device__ __forceinline__ void fma2(ull& d, ull a, ull b) {
    asm("fma.rn.f32x2 %0, %1, %2, %0;" : "+l"(d) : "l"(a), "l"(b));
}
__device__ __forceinline__ float2 upk(ull v) {
    float2 f; asm("mov.b64 {%0,%1}, %2;" : "=f"(f.x), "=f"(f.y) : "l"(v)); return f;
}
// duplicate a float into both lanes of an f32x2 register pair (ALU-pipe movs)
__device__ __forceinline__ ull dup2(float f) {
    ull r; asm("mov.b64 %0, {%1, %1};" : "=l"(r) : "f"(f)); return r;
}
__device__ __forceinline__ unsigned redux_min_u32(unsigned v) {
    unsigned r; asm("redux.sync.min.u32 %0, %1, 0xffffffff;" : "=r"(r) : "r"(v)); return r;
}
__device__ __forceinline__ int redux_min_s32(int v) {
    int r; asm("redux.sync.min.s32 %0, %1, 0xffffffff;" : "=r"(r) : "r"(v)); return r;
}
// Kahan compensated add: s += v with compensation c (4 FADD)
__device__ __forceinline__ void kadd(float& s, float& c, float v) {
    float y = v - c;
    float t = s + y;
    c = (t - s) - y;
    s = t;
}

// ---------------- prep: x (B,1,4,N) -> h (B,N,4) ----------------
__global__ void prep_kernel(const float* __restrict__ x, float* __restrict__ h) {
    int i = blockIdx.x*256 + threadIdx.x;          // over B*N*4
    int c = i & 3, n = (i >> 2) & (NPTS-1), b = i >> 12;
    h[i] = x[((size_t)b*4 + c)*NPTS + n];
}

// ---------------- xx[b,n] = |h_bn|^2 ----------------
template<int C>
__global__ void xx_kernel(const float* __restrict__ h, float* __restrict__ xx) {
    int i = blockIdx.x*256 + threadIdx.x;          // over B*N
    const float4* hp = (const float4*)(h + (size_t)i*C);
    float s = 0.f;
#pragma unroll
    for (int c = 0; c < C/4; c++) { float4 v = hp[c]; s += v.x*v.x + v.y*v.y + v.z*v.z + v.w*v.w; }
    xx[i] = s;
}

// ---------------- pairwise squared distances + per-group node mins ----------------
template<int C>
__global__ __launch_bounds__(256) void dist_kernel(const float* __restrict__ h,
                                                   const float* __restrict__ xx,
                                                   float* __restrict__ dist,
                                                   float* __restrict__ nodemin,
                                                   int zoff) {
    constexpr int KC = (C >= 8) ? 8 : 4;
    __shared__ float As[KC][136];   // 128 rows natural + pad
    __shared__ float Bs[KC][136];
    __shared__ float Ts[64][66];    // transpose staging (float2-aligned dump)
    int bx = blockIdx.x, by = blockIdx.y, b = blockIdx.z + zoff;
    if (bx > by) return;            // symmetry: compute lower triangle, mirror
    int n0 = by * 128, m0 = bx * 128;
    int tid = threadIdx.x;
    int tx = tid & 15, ty = tid >> 4;   // 16x16 threads, 8x8 values each
    ull acc[8][4];
#pragma unroll
    for (int i = 0; i < 8; i++)
#pragma unroll
        for (int j = 0; j < 4; j++) acc[i][j] = 0ull;
    const float* hb = h + (size_t)b*NPTS*C;
    for (int kk = 0; kk < C; kk += KC) {
        for (int e = tid; e < 128*KC; e += 256) {
            int r = e / KC, c = e % KC;
            As[c][r] = hb[(size_t)(n0 + r)*C + kk + c];
            Bs[c][r] = hb[(size_t)(m0 + r)*C + kk + c];
        }
        __syncthreads();
#pragma unroll
        for (int c = 0; c < KC; c++) {
            float4 a0 = *(const float4*)&As[c][ty*8];      // broadcast within warp
            float4 a1 = *(const float4*)&As[c][ty*8+4];
            ull A[8];
            A[0] = dup2(a0.x); A[1] = dup2(a0.y); A[2] = dup2(a0.z); A[3] = dup2(a0.w);
            A[4] = dup2(a1.x); A[5] = dup2(a1.y); A[6] = dup2(a1.z); A[7] = dup2(a1.w);
            const ull* bp = (const ull*)&Bs[c][tx*8];
            ull B[4];
#pragma unroll
            for (int j = 0; j < 4; j++) B[j] = bp[j];
#pragma unroll
            for (int i = 0; i < 8; i++)
#pragma unroll
                for (int j = 0; j < 4; j++) fma2(acc[i][j], A[i], B[j]);
        }
        __syncthreads();
    }
    const float* xxb = xx + b*NPTS;
    float xn[8], xm[8];
#pragma unroll
    for (int i = 0; i < 8; i++) { xn[i] = xxb[n0+ty*8+i]; xm[i] = xxb[m0+tx*8+i]; }
    float ov[8][8];
#pragma unroll
    for (int i = 0; i < 8; i++)
#pragma unroll
        for (int j = 0; j < 4; j++) {
            float2 p = upk(acc[i][j]);
            ov[i][2*j]   = xn[i] + xm[2*j]   - 2.f*p.x;
            ov[i][2*j+1] = xn[i] + xm[2*j+1] - 2.f*p.y;
        }
    float* db = dist + (size_t)b*NPTS*NPTS;
    float* nmb = nodemin + (size_t)b*NPTS*128;
#pragma unroll
    for (int i = 0; i < 8; i++) {
        size_t off = (size_t)(n0+ty*8+i)*NPTS + m0 + tx*8;
        *(float4*)&db[off]   = make_float4(ov[i][0], ov[i][1], ov[i][2], ov[i][3]);
        *(float4*)&db[off+4] = make_float4(ov[i][4], ov[i][5], ov[i][6], ov[i][7]);
        float m = fminf(fminf(fminf(ov[i][0],ov[i][1]), fminf(ov[i][2],ov[i][3])),
                        fminf(fminf(ov[i][4],ov[i][5]), fminf(ov[i][6],ov[i][7])));
        nmb[(size_t)(n0+ty*8+i)*128 + bx*16 + tx] = m;
    }
    if (bx == by) return;
#pragma unroll
    for (int j = 0; j < 8; j++) {
        float m = fminf(fminf(fminf(ov[0][j],ov[1][j]), fminf(ov[2][j],ov[3][j])),
                        fminf(fminf(ov[4][j],ov[5][j]), fminf(ov[6][j],ov[7][j])));
        nmb[(size_t)(m0+tx*8+j)*128 + by*16 + ty] = m;
    }
#pragma unroll
    for (int sr = 0; sr < 2; sr++)
#pragma unroll
        for (int sc = 0; sc < 2; sc++) {
            __syncthreads();
            if ((ty >> 3) == sr && (tx >> 3) == sc) {
#pragma unroll
                for (int i = 0; i < 8; i++)
#pragma unroll
                    for (int j = 0; j < 8; j++)
                        Ts[(tx & 7)*8 + j][(ty & 7)*8 + i] = ov[i][j];
            }
            __syncthreads();
            for (int e = tid; e < 64*32; e += 256) {
                int r = e >> 5, c2 = (e & 31) * 2;
                float2 v = *(float2*)&Ts[r][c2];
                *(float2*)&db[(size_t)(m0 + sc*64 + r)*NPTS + n0 + sr*64 + c2] = v;
            }
        }
}

// ---------------- top-k=20: candidate-pruned tournament, warp per row, NO smem ----------------
__global__ __launch_bounds__(256) void topk_kernel(const float* __restrict__ dist,
                                                   const float* __restrict__ nodemin,
                                                   int* __restrict__ idx,
                                                   int boff) {
    int tid = threadIdx.x;
    int warp = tid >> 5, lane = tid & 31;
    int b = blockIdx.y + boff;
    int n = blockIdx.x * 8 + warp;
    float4 t = *(const float4*)(nodemin + ((size_t)b*NPTS + n)*128 + lane*4);
    float nm[4] = {t.x, t.y, t.z, t.w};
    int mygrp = 0;
    // Phase A: 20 smallest groups by (nodemin, group index)
    for (int kk = 0; kk < KNN; kk++) {
        float lm = fminf(fminf(nm[0], nm[1]), fminf(nm[2], nm[3]));
        unsigned bu = __float_as_uint(lm);
        unsigned tu = bu ^ (((unsigned)((int)bu >> 31)) | 0x80000000u);
        unsigned gm = redux_min_u32(tu);
        int mygid = 0x7FFFFFFF;
        int g = 0;
        if (tu == gm) {
            g = (nm[0]==lm) ? 0 : (nm[1]==lm) ? 1 : (nm[2]==lm) ? 2 : 3;
            mygid = lane*4 + g;
        }
        int win = redux_min_s32(mygid);
        if (mygid == win) {
#pragma unroll
            for (int g2 = 0; g2 < 4; g2++) if (g2 == g) nm[g2] = 3.4e38f;
        }
        if (lane == kk) mygrp = win;
    }
    // Phase B: gather candidate leaves (one parallel LDG round, L2-resident)
    float v[8];
    int base;
    if (lane < KNN) {
        base = mygrp * 8;
        const float4* p = (const float4*)(dist + ((size_t)b*NPTS + n)*NPTS + base);
        float4 a = p[0], c = p[1];
        v[0]=a.x; v[1]=a.y; v[2]=a.z; v[3]=a.w;
        v[4]=c.x; v[5]=c.y; v[6]=c.z; v[7]=c.w;
    } else {
#pragma unroll
        for (int i = 0; i < 8; i++) v[i] = 3.4e38f;
        base = 0x3FFFFF00;
    }
    int* out = idx + ((size_t)b*NPTS + n)*KNN;
    // Phase C: exact top-20 over the candidate leaves
    for (int kk = 0; kk < KNN; kk++) {
        float lm = fminf(fminf(fminf(v[0],v[1]), fminf(v[2],v[3])),
                         fminf(fminf(v[4],v[5]), fminf(v[6],v[7])));
        unsigned bu = __float_as_uint(lm);
        unsigned tu = bu ^ (((unsigned)((int)bu >> 31)) | 0x80000000u);
        unsigned gm = redux_min_u32(tu);
        int mym = 0x7FFFFFFF;
        int li = 0;
        if (tu == gm) {
            li = 7;
#pragma unroll
            for (int i = 6; i >= 0; i--) if (v[i] == lm) li = i;
            mym = base + li;
        }
        int win = redux_min_s32(mym);
        if (mym == win) {
#pragma unroll
            for (int i = 0; i < 8; i++) if (i == li) v[i] = 3.4e38f;
        }
        if (lane == 0) out[kk] = win;
    }
}

// ---------------- u = h W1^T, w = h (W2-W1)^T : 128x64 tile, natural A + reg dup ----------------
template<int C, int O>
__global__ __launch_bounds__(256) void gemm_kernel(const float* __restrict__ h,
                                                   const float* __restrict__ W,
                                                   float* __restrict__ u,
                                                   float* __restrict__ w) {
    constexpr int KC = (C >= 8) ? 8 : 4;
    __shared__ float As[KC][136];
    __shared__ float B1[KC][72];
    __shared__ float B2[KC][72];
    int o0 = blockIdx.x * 64;
    int r0 = blockIdx.y * 128;
    int tid = threadIdx.x, tx = tid & 15, ty = tid >> 4;
    ull au[8][2], aw[8][2];
#pragma unroll
    for (int i = 0; i < 8; i++) { au[i][0]=0ull; au[i][1]=0ull; aw[i][0]=0ull; aw[i][1]=0ull; }
    for (int kk = 0; kk < C; kk += KC) {
        for (int e = tid; e < 128*KC; e += 256) {
            int r = e / KC, c = e % KC;
            As[c][r] = h[(size_t)(r0 + r)*C + kk + c];
        }
        for (int e = tid; e < 64*KC; e += 256) {
            int r = e / KC, c = e % KC;
            float w1 = W[(size_t)(o0 + r)*(2*C) + kk + c];
            float w2 = W[(size_t)(o0 + r)*(2*C) + C + kk + c];
            B1[c][r] = w1;
            B2[c][r] = w2 - w1;
        }
        __syncthreads();
#pragma unroll
        for (int c = 0; c < KC; c++) {
            float4 a0 = *(const float4*)&As[c][ty*8];
            float4 a1 = *(const float4*)&As[c][ty*8+4];
            ull A[8];
            A[0] = dup2(a0.x); A[1] = dup2(a0.y); A[2] = dup2(a0.z); A[3] = dup2(a0.w);
            A[4] = dup2(a1.x); A[5] = dup2(a1.y); A[6] = dup2(a1.z); A[7] = dup2(a1.w);
            ull p0 = *(const ull*)&B1[c][tx*4];
            ull p1 = *(const ull*)&B1[c][tx*4+2];
            ull q0 = *(const ull*)&B2[c][tx*4];
            ull q1 = *(const ull*)&B2[c][tx*4+2];
#pragma unroll
            for (int i = 0; i < 8; i++) {
                fma2(au[i][0], A[i], p0); fma2(au[i][1], A[i], p1);
                fma2(aw[i][0], A[i], q0); fma2(aw[i][1], A[i], q1);
            }
        }
        __syncthreads();
    }
#pragma unroll
    for (int i = 0; i < 8; i++) {
        float2 u0 = upk(au[i][0]), u1 = upk(au[i][1]);
        float2 v0 = upk(aw[i][0]), v1 = upk(aw[i][1]);
        size_t off = (size_t)(r0 + ty*8 + i)*O + o0 + tx*4;
        *(float4*)&u[off] = make_float4(u0.x, u0.y, u1.x, u1.y);
        *(float4*)&w[off] = make_float4(v0.x, v0.y, v1.x, v1.y);
    }
}

// ---------------- gather pass (R11 shape): float4 loads, fp32 node sums + Kahan ----------------
template<int O>
__global__ __launch_bounds__(256) void stats_kernel(const float* __restrict__ u,
                                                    const float* __restrict__ w,
                                                    const int* __restrict__ idx,
                                                    float* __restrict__ ps, float* __restrict__ pq,
                                                    float* __restrict__ ymax, float* __restrict__ ymin,
                                                    int P) {
    constexpr int C4 = O/4;            // channel groups of 4
    constexpr int NL = 256/C4;         // node lanes
    __shared__ int idxs[64*KNN];
    int blk = blockIdx.x, node0 = blk * 64;
    int tid = threadIdx.x;
    int c4 = tid % C4, nl = tid / C4;
    for (int e = tid; e < 64*KNN; e += 256) idxs[e] = idx[(size_t)node0*KNN + e];
    __syncthreads();
    const float4* ub = (const float4*)(u + (size_t)(node0 & ~(NPTS-1))*O);   // batch base
    float S0=0.f,S1=0.f,S2=0.f,S3=0.f,Q0=0.f,Q1=0.f,Q2=0.f,Q3=0.f;
    float cs0=0.f,cs1=0.f,cs2=0.f,cs3=0.f,cq0=0.f,cq1=0.f,cq2=0.f,cq3=0.f;
    for (int ni = nl; ni < 64; ni += NL) {
        int n = node0 + ni;
        float4 wv = *(const float4*)(w + (size_t)n*O + c4*4);
        float4 mx = make_float4(-3.4e38f,-3.4e38f,-3.4e38f,-3.4e38f);
        float4 mn = make_float4( 3.4e38f, 3.4e38f, 3.4e38f, 3.4e38f);
        float s0=0.f,s1=0.f,s2=0.f,s3=0.f,q0=0.f,q1=0.f,q2=0.f,q3=0.f;
#pragma unroll
        for (int k = 0; k < KNN; k++) {
            int r = idxs[ni*KNN + k];
            float4 y = ub[(size_t)r*C4 + c4];
            y.x += wv.x; y.y += wv.y; y.z += wv.z; y.w += wv.w;
            s0 += y.x; q0 += y.x*y.x; mx.x = fmaxf(mx.x,y.x); mn.x = fminf(mn.x,y.x);
            s1 += y.y; q1 += y.y*y.y; mx.y = fmaxf(mx.y,y.y); mn.y = fminf(mn.y,y.y);
            s2 += y.z; q2 += y.z*y.z; mx.z = fmaxf(mx.z,y.z); mn.z = fminf(mn.z,y.z);
            s3 += y.w; q3 += y.w*y.w; mx.w = fmaxf(mx.w,y.w); mn.w = fminf(mn.w,y.w);
        }
        *(float4*)(ymax + (size_t)n*O + c4*4) = mx;
        *(float4*)(ymin + (size_t)n*O + c4*4) = mn;
        kadd(S0, cs0, s0); kadd(Q0, cq0, q0);
        kadd(S1, cs1, s1); kadd(Q1, cq1, q1);
        kadd(S2, cs2, s2); kadd(Q2, cq2, q2);
        kadd(S3, cs3, s3); kadd(Q3, cq3, q3);
    }
    int col = blk*NL + nl;
    ps[(size_t)(c4*4+0)*P + col] = S0 - cs0;  pq[(size_t)(c4*4+0)*P + col] = Q0 - cq0;
    ps[(size_t)(c4*4+1)*P + col] = S1 - cs1;  pq[(size_t)(c4*4+1)*P + col] = Q1 - cq1;
    ps[(size_t)(c4*4+2)*P + col] = S2 - cs2;  pq[(size_t)(c4*4+2)*P + col] = Q2 - cq2;
    ps[(size_t)(c4*4+3)*P + col] = S3 - cs3;  pq[(size_t)(c4*4+3)*P + col] = Q3 - cq3;
}

// ---------------- reduce fp32 partials in double -> scale/shift per channel ----------------
__global__ __launch_bounds__(128) void bnstats_kernel(const float* __restrict__ ps,
                                                      const float* __restrict__ pq,
                                                      const float* __restrict__ g,
                                                      const float* __restrict__ bt,
                                                      float* __restrict__ scale,
                                                      float* __restrict__ shift, int P) {
    __shared__ double shs[4], shq[4];
    int o = blockIdx.x;
    int tid = threadIdx.x, lane = tid & 31, wp = tid >> 5;
    double s = 0., q = 0.;
    for (int p = tid; p < P; p += 128) {
        s += (double)ps[(size_t)o*P + p];
        q += (double)pq[(size_t)o*P + p];
    }
#pragma unroll
    for (int off = 16; off; off >>= 1) {
        s += __shfl_down_sync(0xffffffffu, s, off);
        q += __shfl_down_sync(0xffffffffu, q, off);
    }
    if (lane == 0) { shs[wp] = s; shq[wp] = q; }
    __syncthreads();
    if (tid == 0) {
        s = shs[0] + shs[1] + shs[2] + shs[3];
        q = shq[0] + shq[1] + shq[2] + shq[3];
        const double inv = 1.0 / (double)(BATCH*NPTS*KNN);
        double mean = s * inv;
        double var  = q * inv - mean*mean;
        double rs   = 1.0 / sqrt(var + 1e-5);
        double sc   = (double)g[o] * rs;
        scale[o] = (float)sc;
        shift[o] = (float)((double)bt[o] - mean*sc);
    }
}

// ---------------- finalize: BN + LeakyReLU on the k-extremum (monotone trick) ----------------
template<int O>
__global__ void finalize_kernel(const float4* __restrict__ ymax, const float4* __restrict__ ymin,
                                const float4* __restrict__ scale, const float4* __restrict__ shift,
                                float4* __restrict__ hout) {
    int i = blockIdx.x*256 + threadIdx.x;           // over BN*O/4
    int o4 = i & (O/4 - 1);
    float4 sc = scale[o4], sh = shift[o4];
    float4 mx = ymax[i], mn = ymin[i];
    float4 r;
    float v;
    v = (sc.x >= 0.f ? mx.x : mn.x)*sc.x + sh.x; r.x = (v >= 0.f) ? v : 0.2f*v;
    v = (sc.y >= 0.f ? mx.y : mn.y)*sc.y + sh.y; r.y = (v >= 0.f) ? v : 0.2f*v;
    v = (sc.z >= 0.f ? mx.z : mn.z)*sc.z + sh.z; r.z = (v >= 0.f) ? v : 0.2f*v;
    v = (sc.w >= 0.f ? mx.w : mn.w)*sc.w + sh.w; r.w = (v >= 0.f) ? v : 0.2f*v;
    hout[i] = r;
}

// ---------------- final max over N (two deterministic stages) ----------------
__global__ void pmax_kernel(const float* __restrict__ h, float* __restrict__ part) {
    int b = blockIdx.y, ch = blockIdx.x, o = threadIdx.x;
    const float* hp = h + ((size_t)b*NPTS + ch*64)*256 + o;
    float m = -3.4e38f;
    for (int n = 0; n < 64; n++) m = fmaxf(m, hp[(size_t)n*256]);
    part[((size_t)b*16 + ch)*256 + o] = m;
}
__global__ void fmax_kernel(const float* __restrict__ part, float* __restrict__ out) {
    int b = blockIdx.x, o = threadIdx.x;
    float m = -3.4e38f;
    for (int c = 0; c < 16; c++) m = fmaxf(m, part[((size_t)b*16 + c)*256 + o]);
    out[(size_t)b*256 + o] = m;
}

// ---------------- host orchestration ----------------
struct Scratch {
    float *hA, *hB, *u, *w, *ymax, *ymin, *xx, *dist, *nodemin, *ps, *pq, *scale, *shift, *part;
    int* idx;
};

// side streams + events: s2 = gemm overlap, s3 = topk half-pipeline
static cudaStream_t g_s2 = nullptr, g_s3 = nullptr;
static cudaEvent_t  g_evF[4], g_evJ[4], g_evDA[4], g_evTA[4];

template<int C, int O>
static void run_layer(const float* hin, float* hout, const float* W,
                      const float* g, const float* bt, const Scratch& Z, int li) {
    int P = 262144 / O;
    // fork: gemm(hin, W) is independent of the xx->dist->topk chain
    cudaEventRecord(g_evF[li], 0);
    cudaStreamWaitEvent(g_s2, g_evF[li], 0);
    gemm_kernel<C, O><<<dim3(O/64, BN/128), 256, 0, g_s2>>>(hin, W, Z.u, Z.w);
    cudaEventRecord(g_evJ[li], g_s2);

    xx_kernel<C><<<BN/256, 256>>>(hin, Z.xx);
    // pipelined halves: topk(first 8 batches) overlaps dist(last 8 batches)
    dist_kernel<C><<<dim3(8, 8, 8), 256>>>(hin, Z.xx, Z.dist, Z.nodemin, 0);
    cudaEventRecord(g_evDA[li], 0);
    dist_kernel<C><<<dim3(8, 8, 8), 256>>>(hin, Z.xx, Z.dist, Z.nodemin, 8);
    cudaStreamWaitEvent(g_s3, g_evDA[li], 0);
    topk_kernel<<<dim3(NPTS/8, 8), 256, 0, g_s3>>>(Z.dist, Z.nodemin, Z.idx, 0);
    cudaEventRecord(g_evTA[li], g_s3);
    topk_kernel<<<dim3(NPTS/8, 8), 256>>>(Z.dist, Z.nodemin, Z.idx, 8);

    // join before the gather needs idx (both halves) and u/w
    cudaStreamWaitEvent(0, g_evTA[li], 0);
    cudaStreamWaitEvent(0, g_evJ[li], 0);
    stats_kernel<O><<<BN/64, 256>>>(Z.u, Z.w, Z.idx, Z.ps, Z.pq, Z.ymax, Z.ymin, P);
    bnstats_kernel<<<O, 128>>>(Z.ps, Z.pq, g, bt, Z.scale, Z.shift, P);
    finalize_kernel<O><<<(BN*O/4)/256, 256>>>((const float4*)Z.ymax, (const float4*)Z.ymin,
                                              (const float4*)Z.scale, (const float4*)Z.shift,
                                              (float4*)hout);
}

extern "C" void kernel_launch(void* const* d_in, const int* in_sizes, int n_in,
                              void* d_out, int out_size) {
    if (g_s2 == nullptr) {                          // one-time resource setup (first,
        cudaStreamCreateWithFlags(&g_s2, cudaStreamNonBlocking);   // uncaptured call)
        cudaStreamCreateWithFlags(&g_s3, cudaStreamNonBlocking);
        for (int i = 0; i < 4; i++) {
            cudaEventCreateWithFlags(&g_evF[i],  cudaEventDisableTiming);
            cudaEventCreateWithFlags(&g_evJ[i],  cudaEventDisableTiming);
            cudaEventCreateWithFlags(&g_evDA[i], cudaEventDisableTiming);
            cudaEventCreateWithFlags(&g_evTA[i], cudaEventDisableTiming);
        }
    }
    const float* x = (const float*)d_in[0];
    const float* Wp[4]; const float* gp[4]; const float* bp[4];
    for (int i = 0; i < 4; i++) {
        Wp[i] = (const float*)d_in[1 + 3*i];
        gp[i] = (const float*)d_in[2 + 3*i];
        bp[i] = (const float*)d_in[3 + 3*i];
    }
    Scratch Z;
    cudaGetSymbolAddress((void**)&Z.hA,      g_hA);
    cudaGetSymbolAddress((void**)&Z.hB,      g_hB);
    cudaGetSymbolAddress((void**)&Z.u,       g_u);
    cudaGetSymbolAddress((void**)&Z.w,       g_w);
    cudaGetSymbolAddress((void**)&Z.ymax,    g_ymax);
    cudaGetSymbolAddress((void**)&Z.ymin,    g_ymin);
    cudaGetSymbolAddress((void**)&Z.xx,      g_xx);
    cudaGetSymbolAddress((void**)&Z.dist,    g_dist);
    cudaGetSymbolAddress((void**)&Z.nodemin, g_nodemin);
    cudaGetSymbolAddress((void**)&Z.ps,      g_ps);
    cudaGetSymbolAddress((void**)&Z.pq,      g_pq);
    cudaGetSymbolAddress((void**)&Z.scale,   g_scale);
    cudaGetSymbolAddress((void**)&Z.shift,   g_shift);
    cudaGetSymbolAddress((void**)&Z.part,    g_part);
    cudaGetSymbolAddress((void**)&Z.idx,     g_idx);

    prep_kernel<<<(BN*4)/256, 256>>>(x, Z.hA);

    run_layer<4,   64 >(Z.hA, Z.hB, Wp[0], gp[0], bp[0], Z, 0);
    run_layer<64,  64 >(Z.hB, Z.hA, Wp[1], gp[1], bp[1], Z, 1);
    run_layer<64,  128>(Z.hA, Z.hB, Wp[2], gp[2], bp[2], Z, 2);
    run_layer<128, 256>(Z.hB, Z.hA, Wp[3], gp[3], bp[3], Z, 3);

    pmax_kernel<<<dim3(16, BATCH), 256>>>(Z.hA, Z.part);
    fmax_kernel<<<BATCH, 256>>>(Z.part, (float*)d_out);
}

// round 16
// speedup vs baseline: 1.1146x; 1.0340x over previous
#include <cuda_runtime.h>
#include <cstddef>

#define BATCH 16
#define NPTS  1024
#define KNN   20
#define BN    (BATCH*NPTS)

typedef unsigned long long ull;

// ---------------- scratch (static device globals; allocation-free) ----------------
__device__ float g_hA[BN*256];
__device__ float g_hB[BN*256];
__device__ float g_u [BN*256];
__device__ float g_w [BN*256];
__device__ float g_ymax[BN*256];
__device__ float g_ymin[BN*256];
__device__ float g_xx[BN];
__device__ float g_dist[BATCH*NPTS*NPTS];       // 67 MB, L2-resident
__device__ float g_nodemin[BN*128];             // per-row mins of 8-col groups
__device__ int   g_idx[BN*KNN];
__device__ float g_ps[262144];                  // stats partials [o][P], O*P == 262144
__device__ float g_pq[262144];
__device__ float g_scale[256];
__device__ float g_shift[256];
__device__ float g_part[BATCH*16*256];

// ---------------- f32x2 helpers ----------------
__device__ __forceinline__ void fma2(ull& d, ull a, ull b) {
    asm("fma.rn.f32x2 %0, %1, %2, %0;" : "+l"(d) : "l"(a), "l"(b));
}
__device__ __forceinline__ float2 upk(ull v) {
    float2 f; asm("mov.b64 {%0,%1}, %2;" : "=f"(f.x), "=f"(f.y) : "l"(v)); return f;
}
// duplicate a float into both lanes of an f32x2 register pair (ALU-pipe movs)
__device__ __forceinline__ ull dup2(float f) {
    ull r; asm("mov.b64 %0, {%1, %1};" : "=l"(r) : "f"(f)); return r;
}
__device__ __forceinline__ unsigned redux_min_u32(unsigned v) {
    unsigned r; asm("redux.sync.min.u32 %0, %1, 0xffffffff;" : "=r"(r) : "r"(v)); return r;
}
__device__ __forceinline__ int redux_min_s32(int v) {
    int r; asm("redux.sync.min.s32 %0, %1, 0xffffffff;" : "=r"(r) : "r"(v)); return r;
}
// Kahan compensated add: s += v with compensation c (4 FADD)
__device__ __forceinline__ void kadd(float& s, float& c, float v) {
    float y = v - c;
    float t = s + y;
    c = (t - s) - y;
    s = t;
}

// ---------------- prep: x (B,1,4,N) -> h (B,N,4) ----------------
__global__ void prep_kernel(const float* __restrict__ x, float* __restrict__ h) {
    int i = blockIdx.x*256 + threadIdx.x;          // over B*N*4
    int c = i & 3, n = (i >> 2) & (NPTS-1), b = i >> 12;
    h[i] = x[((size_t)b*4 + c)*NPTS + n];
}

// ---------------- xx[b,n] = |h_bn|^2 ----------------
template<int C>
__global__ void xx_kernel(const float* __restrict__ h, float* __restrict__ xx) {
    int i = blockIdx.x*256 + threadIdx.x;          // over B*N
    const float4* hp = (const float4*)(h + (size_t)i*C);
    float s = 0.f;
#pragma unroll
    for (int c = 0; c < C/4; c++) { float4 v = hp[c]; s += v.x*v.x + v.y*v.y + v.z*v.z + v.w*v.w; }
    xx[i] = s;
}

// ---------------- C=4 specialized dist: 64x64 tile, 4x4/thread, full matrix ----------------
// No symmetry/mirror/transpose: FLOPs are trivial at C=4; the old kernel was
// latency-bound at 21% occupancy (126 regs). This shape: ~48 regs -> 4-5
// blocks/SM, coalesced float4 stores only. dist[n][m]==dist[m][n] bitwise
// (commutative adds, same-order fma chain), so results match the mirrored path.
__global__ __launch_bounds__(256) void dist4_kernel(const float* __restrict__ h,
                                                    const float* __restrict__ xx,
                                                    float* __restrict__ dist,
                                                    float* __restrict__ nodemin,
                                                    int zoff) {
    __shared__ float As[4][72];
    __shared__ float Bs[4][72];
    int bx = blockIdx.x, by = blockIdx.y, b = blockIdx.z + zoff;
    int n0 = by * 64, m0 = bx * 64;
    int tid = threadIdx.x, tx = tid & 15, ty = tid >> 4;
    const float* hb = h + (size_t)b*NPTS*4;
    if (tid < 64) {
        float4 v = *(const float4*)(hb + (size_t)(n0 + tid)*4);
        As[0][tid] = v.x; As[1][tid] = v.y; As[2][tid] = v.z; As[3][tid] = v.w;
    } else if (tid < 128) {
        int r = tid - 64;
        float4 v = *(const float4*)(hb + (size_t)(m0 + r)*4);
        Bs[0][r] = v.x; Bs[1][r] = v.y; Bs[2][r] = v.z; Bs[3][r] = v.w;
    }
    __syncthreads();
    ull acc[4][2];
#pragma unroll
    for (int i = 0; i < 4; i++) { acc[i][0] = 0ull; acc[i][1] = 0ull; }
#pragma unroll
    for (int c = 0; c < 4; c++) {
        ull A0 = dup2(As[c][ty*4+0]);
        ull A1 = dup2(As[c][ty*4+1]);
        ull A2 = dup2(As[c][ty*4+2]);
        ull A3 = dup2(As[c][ty*4+3]);
        ull B0 = *(const ull*)&Bs[c][tx*4];
        ull B1 = *(const ull*)&Bs[c][tx*4+2];
        fma2(acc[0][0], A0, B0); fma2(acc[0][1], A0, B1);
        fma2(acc[1][0], A1, B0); fma2(acc[1][1], A1, B1);
        fma2(acc[2][0], A2, B0); fma2(acc[2][1], A2, B1);
        fma2(acc[3][0], A3, B0); fma2(acc[3][1], A3, B1);
    }
    const float* xxb = xx + b*NPTS;
    float xn[4], xm[4];
#pragma unroll
    for (int i = 0; i < 4; i++) { xn[i] = xxb[n0+ty*4+i]; xm[i] = xxb[m0+tx*4+i]; }
    float* db = dist + (size_t)b*NPTS*NPTS;
    float* nmb = nodemin + (size_t)b*NPTS*128;
#pragma unroll
    for (int i = 0; i < 4; i++) {
        float2 p0 = upk(acc[i][0]), p1 = upk(acc[i][1]);
        float4 o;
        o.x = xn[i] + xm[0] - 2.f*p0.x;
        o.y = xn[i] + xm[1] - 2.f*p0.y;
        o.z = xn[i] + xm[2] - 2.f*p1.x;
        o.w = xn[i] + xm[3] - 2.f*p1.y;
        *(float4*)&db[(size_t)(n0+ty*4+i)*NPTS + m0 + tx*4] = o;
        // 8-col group min: pair tx with tx^1 (same warp, lane bit0 == tx bit0)
        float m = fminf(fminf(o.x, o.y), fminf(o.z, o.w));
        float m8 = fminf(m, __shfl_xor_sync(0xffffffffu, m, 1));
        if ((tx & 1) == 0)
            nmb[(size_t)(n0+ty*4+i)*128 + bx*8 + (tx >> 1)] = m8;
    }
}

// ---------------- pairwise squared distances + per-group node mins (C>=64) ----------------
template<int C>
__global__ __launch_bounds__(256) void dist_kernel(const float* __restrict__ h,
                                                   const float* __restrict__ xx,
                                                   float* __restrict__ dist,
                                                   float* __restrict__ nodemin,
                                                   int zoff) {
    constexpr int KC = 8;
    __shared__ float As[KC][136];   // 128 rows natural + pad
    __shared__ float Bs[KC][136];
    __shared__ float Ts[64][66];    // transpose staging (float2-aligned dump)
    int bx = blockIdx.x, by = blockIdx.y, b = blockIdx.z + zoff;
    if (bx > by) return;            // symmetry: compute lower triangle, mirror
    int n0 = by * 128, m0 = bx * 128;
    int tid = threadIdx.x;
    int tx = tid & 15, ty = tid >> 4;   // 16x16 threads, 8x8 values each
    ull acc[8][4];
#pragma unroll
    for (int i = 0; i < 8; i++)
#pragma unroll
        for (int j = 0; j < 4; j++) acc[i][j] = 0ull;
    const float* hb = h + (size_t)b*NPTS*C;
    for (int kk = 0; kk < C; kk += KC) {
        for (int e = tid; e < 128*KC; e += 256) {
            int r = e / KC, c = e % KC;
            As[c][r] = hb[(size_t)(n0 + r)*C + kk + c];
            Bs[c][r] = hb[(size_t)(m0 + r)*C + kk + c];
        }
        __syncthreads();
#pragma unroll
        for (int c = 0; c < KC; c++) {
            float4 a0 = *(const float4*)&As[c][ty*8];      // broadcast within warp
            float4 a1 = *(const float4*)&As[c][ty*8+4];
            ull A[8];
            A[0] = dup2(a0.x); A[1] = dup2(a0.y); A[2] = dup2(a0.z); A[3] = dup2(a0.w);
            A[4] = dup2(a1.x); A[5] = dup2(a1.y); A[6] = dup2(a1.z); A[7] = dup2(a1.w);
            const ull* bp = (const ull*)&Bs[c][tx*8];
            ull B[4];
#pragma unroll
            for (int j = 0; j < 4; j++) B[j] = bp[j];
#pragma unroll
            for (int i = 0; i < 8; i++)
#pragma unroll
                for (int j = 0; j < 4; j++) fma2(acc[i][j], A[i], B[j]);
        }
        __syncthreads();
    }
    const float* xxb = xx + b*NPTS;
    float xn[8], xm[8];
#pragma unroll
    for (int i = 0; i < 8; i++) { xn[i] = xxb[n0+ty*8+i]; xm[i] = xxb[m0+tx*8+i]; }
    float ov[8][8];
#pragma unroll
    for (int i = 0; i < 8; i++)
#pragma unroll
        for (int j = 0; j < 4; j++) {
            float2 p = upk(acc[i][j]);
            ov[i][2*j]   = xn[i] + xm[2*j]   - 2.f*p.x;
            ov[i][2*j+1] = xn[i] + xm[2*j+1] - 2.f*p.y;
        }
    float* db = dist + (size_t)b*NPTS*NPTS;
    float* nmb = nodemin + (size_t)b*NPTS*128;
#pragma unroll
    for (int i = 0; i < 8; i++) {
        size_t off = (size_t)(n0+ty*8+i)*NPTS + m0 + tx*8;
        *(float4*)&db[off]   = make_float4(ov[i][0], ov[i][1], ov[i][2], ov[i][3]);
        *(float4*)&db[off+4] = make_float4(ov[i][4], ov[i][5], ov[i][6], ov[i][7]);
        float m = fminf(fminf(fminf(ov[i][0],ov[i][1]), fminf(ov[i][2],ov[i][3])),
                        fminf(fminf(ov[i][4],ov[i][5]), fminf(ov[i][6],ov[i][7])));
        nmb[(size_t)(n0+ty*8+i)*128 + bx*16 + tx] = m;
    }
    if (bx == by) return;
#pragma unroll
    for (int j = 0; j < 8; j++) {
        float m = fminf(fminf(fminf(ov[0][j],ov[1][j]), fminf(ov[2][j],ov[3][j])),
                        fminf(fminf(ov[4][j],ov[5][j]), fminf(ov[6][j],ov[7][j])));
        nmb[(size_t)(m0+tx*8+j)*128 + by*16 + ty] = m;
    }
#pragma unroll
    for (int sr = 0; sr < 2; sr++)
#pragma unroll
        for (int sc = 0; sc < 2; sc++) {
            __syncthreads();
            if ((ty >> 3) == sr && (tx >> 3) == sc) {
#pragma unroll
                for (int i = 0; i < 8; i++)
#pragma unroll
                    for (int j = 0; j < 8; j++)
                        Ts[(tx & 7)*8 + j][(ty & 7)*8 + i] = ov[i][j];
            }
            __syncthreads();
            for (int e = tid; e < 64*32; e += 256) {
                int r = e >> 5, c2 = (e & 31) * 2;
                float2 v = *(float2*)&Ts[r][c2];
                *(float2*)&db[(size_t)(m0 + sc*64 + r)*NPTS + n0 + sr*64 + c2] = v;
            }
        }
}

// ---------------- top-k=20: candidate-pruned tournament, warp per row, NO smem ----------------
__global__ __launch_bounds__(256) void topk_kernel(const float* __restrict__ dist,
                                                   const float* __restrict__ nodemin,
                                                   int* __restrict__ idx,
                                                   int boff) {
    int tid = threadIdx.x;
    int warp = tid >> 5, lane = tid & 31;
    int b = blockIdx.y + boff;
    int n = blockIdx.x * 8 + warp;
    float4 t = *(const float4*)(nodemin + ((size_t)b*NPTS + n)*128 + lane*4);
    float nm[4] = {t.x, t.y, t.z, t.w};
    int mygrp = 0;
    // Phase A: 20 smallest groups by (nodemin, group index)
    for (int kk = 0; kk < KNN; kk++) {
        float lm = fminf(fminf(nm[0], nm[1]), fminf(nm[2], nm[3]));
        unsigned bu = __float_as_uint(lm);
        unsigned tu = bu ^ (((unsigned)((int)bu >> 31)) | 0x80000000u);
        unsigned gm = redux_min_u32(tu);
        int mygid = 0x7FFFFFFF;
        int g = 0;
        if (tu == gm) {
            g = (nm[0]==lm) ? 0 : (nm[1]==lm) ? 1 : (nm[2]==lm) ? 2 : 3;
            mygid = lane*4 + g;
        }
        int win = redux_min_s32(mygid);
        if (mygid == win) {
#pragma unroll
            for (int g2 = 0; g2 < 4; g2++) if (g2 == g) nm[g2] = 3.4e38f;
        }
        if (lane == kk) mygrp = win;
    }
    // Phase B: gather candidate leaves (one parallel LDG round, L2-resident)
    float v[8];
    int base;
    if (lane < KNN) {
        base = mygrp * 8;
        const float4* p = (const float4*)(dist + ((size_t)b*NPTS + n)*NPTS + base);
        float4 a = p[0], c = p[1];
        v[0]=a.x; v[1]=a.y; v[2]=a.z; v[3]=a.w;
        v[4]=c.x; v[5]=c.y; v[6]=c.z; v[7]=c.w;
    } else {
#pragma unroll
        for (int i = 0; i < 8; i++) v[i] = 3.4e38f;
        base = 0x3FFFFF00;
    }
    int* out = idx + ((size_t)b*NPTS + n)*KNN;
    // Phase C: exact top-20 over the candidate leaves
    for (int kk = 0; kk < KNN; kk++) {
        float lm = fminf(fminf(fminf(v[0],v[1]), fminf(v[2],v[3])),
                         fminf(fminf(v[4],v[5]), fminf(v[6],v[7])));
        unsigned bu = __float_as_uint(lm);
        unsigned tu = bu ^ (((unsigned)((int)bu >> 31)) | 0x80000000u);
        unsigned gm = redux_min_u32(tu);
        int mym = 0x7FFFFFFF;
        int li = 0;
        if (tu == gm) {
            li = 7;
#pragma unroll
            for (int i = 6; i >= 0; i--) if (v[i] == lm) li = i;
            mym = base + li;
        }
        int win = redux_min_s32(mym);
        if (mym == win) {
#pragma unroll
            for (int i = 0; i < 8; i++) if (i == li) v[i] = 3.4e38f;
        }
        if (lane == 0) out[kk] = win;
    }
}

// ---------------- u = h W1^T, w = h (W2-W1)^T : 128x64 tile, natural A + reg dup ----------------
template<int C, int O>
__global__ __launch_bounds__(256) void gemm_kernel(const float* __restrict__ h,
                                                   const float* __restrict__ W,
                                                   float* __restrict__ u,
                                                   float* __restrict__ w) {
    constexpr int KC = (C >= 8) ? 8 : 4;
    __shared__ float As[KC][136];
    __shared__ float B1[KC][72];
    __shared__ float B2[KC][72];
    int o0 = blockIdx.x * 64;
    int r0 = blockIdx.y * 128;
    int tid = threadIdx.x, tx = tid & 15, ty = tid >> 4;
    ull au[8][2], aw[8][2];
#pragma unroll
    for (int i = 0; i < 8; i++) { au[i][0]=0ull; au[i][1]=0ull; aw[i][0]=0ull; aw[i][1]=0ull; }
    for (int kk = 0; kk < C; kk += KC) {
        for (int e = tid; e < 128*KC; e += 256) {
            int r = e / KC, c = e % KC;
            As[c][r] = h[(size_t)(r0 + r)*C + kk + c];
        }
        for (int e = tid; e < 64*KC; e += 256) {
            int r = e / KC, c = e % KC;
            float w1 = W[(size_t)(o0 + r)*(2*C) + kk + c];
            float w2 = W[(size_t)(o0 + r)*(2*C) + C + kk + c];
            B1[c][r] = w1;
            B2[c][r] = w2 - w1;
        }
        __syncthreads();
#pragma unroll
        for (int c = 0; c < KC; c++) {
            float4 a0 = *(const float4*)&As[c][ty*8];
            float4 a1 = *(const float4*)&As[c][ty*8+4];
            ull A[8];
            A[0] = dup2(a0.x); A[1] = dup2(a0.y); A[2] = dup2(a0.z); A[3] = dup2(a0.w);
            A[4] = dup2(a1.x); A[5] = dup2(a1.y); A[6] = dup2(a1.z); A[7] = dup2(a1.w);
            ull p0 = *(const ull*)&B1[c][tx*4];
            ull p1 = *(const ull*)&B1[c][tx*4+2];
            ull q0 = *(const ull*)&B2[c][tx*4];
            ull q1 = *(const ull*)&B2[c][tx*4+2];
#pragma unroll
            for (int i = 0; i < 8; i++) {
                fma2(au[i][0], A[i], p0); fma2(au[i][1], A[i], p1);
                fma2(aw[i][0], A[i], q0); fma2(aw[i][1], A[i], q1);
            }
        }
        __syncthreads();
    }
#pragma unroll
    for (int i = 0; i < 8; i++) {
        float2 u0 = upk(au[i][0]), u1 = upk(au[i][1]);
        float2 v0 = upk(aw[i][0]), v1 = upk(aw[i][1]);
        size_t off = (size_t)(r0 + ty*8 + i)*O + o0 + tx*4;
        *(float4*)&u[off] = make_float4(u0.x, u0.y, u1.x, u1.y);
        *(float4*)&w[off] = make_float4(v0.x, v0.y, v1.x, v1.y);
    }
}

// ---------------- gather pass (R11 shape): float4 loads, fp32 node sums + Kahan ----------------
template<int O>
__global__ __launch_bounds__(256) void stats_kernel(const float* __restrict__ u,
                                                    const float* __restrict__ w,
                                                    const int* __restrict__ idx,
                                                    float* __restrict__ ps, float* __restrict__ pq,
                                                    float* __restrict__ ymax, float* __restrict__ ymin,
                                                    int P) {
    constexpr int C4 = O/4;            // channel groups of 4
    constexpr int NL = 256/C4;         // node lanes
    __shared__ int idxs[64*KNN];
    int blk = blockIdx.x, node0 = blk * 64;
    int tid = threadIdx.x;
    int c4 = tid % C4, nl = tid / C4;
    for (int e = tid; e < 64*KNN; e += 256) idxs[e] = idx[(size_t)node0*KNN + e];
    __syncthreads();
    const float4* ub = (const float4*)(u + (size_t)(node0 & ~(NPTS-1))*O);   // batch base
    float S0=0.f,S1=0.f,S2=0.f,S3=0.f,Q0=0.f,Q1=0.f,Q2=0.f,Q3=0.f;
    float cs0=0.f,cs1=0.f,cs2=0.f,cs3=0.f,cq0=0.f,cq1=0.f,cq2=0.f,cq3=0.f;
    for (int ni = nl; ni < 64; ni += NL) {
        int n = node0 + ni;
        float4 wv = *(const float4*)(w + (size_t)n*O + c4*4);
        float4 mx = make_float4(-3.4e38f,-3.4e38f,-3.4e38f,-3.4e38f);
        float4 mn = make_float4( 3.4e38f, 3.4e38f, 3.4e38f, 3.4e38f);
        float s0=0.f,s1=0.f,s2=0.f,s3=0.f,q0=0.f,q1=0.f,q2=0.f,q3=0.f;
#pragma unroll
        for (int k = 0; k < KNN; k++) {
            int r = idxs[ni*KNN + k];
            float4 y = ub[(size_t)r*C4 + c4];
            y.x += wv.x; y.y += wv.y; y.z += wv.z; y.w += wv.w;
            s0 += y.x; q0 += y.x*y.x; mx.x = fmaxf(mx.x,y.x); mn.x = fminf(mn.x,y.x);
            s1 += y.y; q1 += y.y*y.y; mx.y = fmaxf(mx.y,y.y); mn.y = fminf(mn.y,y.y);
            s2 += y.z; q2 += y.z*y.z; mx.z = fmaxf(mx.z,y.z); mn.z = fminf(mn.z,y.z);
            s3 += y.w; q3 += y.w*y.w; mx.w = fmaxf(mx.w,y.w); mn.w = fminf(mn.w,y.w);
        }
        *(float4*)(ymax + (size_t)n*O + c4*4) = mx;
        *(float4*)(ymin + (size_t)n*O + c4*4) = mn;
        kadd(S0, cs0, s0); kadd(Q0, cq0, q0);
        kadd(S1, cs1, s1); kadd(Q1, cq1, q1);
        kadd(S2, cs2, s2); kadd(Q2, cq2, q2);
        kadd(S3, cs3, s3); kadd(Q3, cq3, q3);
    }
    int col = blk*NL + nl;
    ps[(size_t)(c4*4+0)*P + col] = S0 - cs0;  pq[(size_t)(c4*4+0)*P + col] = Q0 - cq0;
    ps[(size_t)(c4*4+1)*P + col] = S1 - cs1;  pq[(size_t)(c4*4+1)*P + col] = Q1 - cq1;
    ps[(size_t)(c4*4+2)*P + col] = S2 - cs2;  pq[(size_t)(c4*4+2)*P + col] = Q2 - cq2;
    ps[(size_t)(c4*4+3)*P + col] = S3 - cs3;  pq[(size_t)(c4*4+3)*P + col] = Q3 - cq3;
}

// ---------------- reduce fp32 partials in double -> scale/shift per channel ----------------
__global__ __launch_bounds__(128) void bnstats_kernel(const float* __restrict__ ps,
                                                      const float* __restrict__ pq,
                                                      const float* __restrict__ g,
                                                      const float* __restrict__ bt,
                                                      float* __restrict__ scale,
                                                      float* __restrict__ shift, int P) {
    __shared__ double shs[4], shq[4];
    int o = blockIdx.x;
    int tid = threadIdx.x, lane = tid & 31, wp = tid >> 5;
    double s = 0., q = 0.;
    for (int p = tid; p < P; p += 128) {
        s += (double)ps[(size_t)o*P + p];
        q += (double)pq[(size_t)o*P + p];
    }
#pragma unroll
    for (int off = 16; off; off >>= 1) {
        s += __shfl_down_sync(0xffffffffu, s, off);
        q += __shfl_down_sync(0xffffffffu, q, off);
    }
    if (lane == 0) { shs[wp] = s; shq[wp] = q; }
    __syncthreads();
    if (tid == 0) {
        s = shs[0] + shs[1] + shs[2] + shs[3];
        q = shq[0] + shq[1] + shq[2] + shq[3];
        const double inv = 1.0 / (double)(BATCH*NPTS*KNN);
        double mean = s * inv;
        double var  = q * inv - mean*mean;
        double rs   = 1.0 / sqrt(var + 1e-5);
        double sc   = (double)g[o] * rs;
        scale[o] = (float)sc;
        shift[o] = (float)((double)bt[o] - mean*sc);
    }
}

// ---------------- finalize: BN + LeakyReLU on the k-extremum (monotone trick) ----------------
template<int O>
__global__ void finalize_kernel(const float4* __restrict__ ymax, const float4* __restrict__ ymin,
                                const float4* __restrict__ scale, const float4* __restrict__ shift,
                                float4* __restrict__ hout) {
    int i = blockIdx.x*256 + threadIdx.x;           // over BN*O/4
    int o4 = i & (O/4 - 1);
    float4 sc = scale[o4], sh = shift[o4];
    float4 mx = ymax[i], mn = ymin[i];
    float4 r;
    float v;
    v = (sc.x >= 0.f ? mx.x : mn.x)*sc.x + sh.x; r.x = (v >= 0.f) ? v : 0.2f*v;
    v = (sc.y >= 0.f ? mx.y : mn.y)*sc.y + sh.y; r.y = (v >= 0.f) ? v : 0.2f*v;
    v = (sc.z >= 0.f ? mx.z : mn.z)*sc.z + sh.z; r.z = (v >= 0.f) ? v : 0.2f*v;
    v = (sc.w >= 0.f ? mx.w : mn.w)*sc.w + sh.w; r.w = (v >= 0.f) ? v : 0.2f*v;
    hout[i] = r;
}

// ---------------- final max over N (two deterministic stages) ----------------
__global__ void pmax_kernel(const float* __restrict__ h, float* __restrict__ part) {
    int b = blockIdx.y, ch = blockIdx.x, o = threadIdx.x;
    const float* hp = h + ((size_t)b*NPTS + ch*64)*256 + o;
    float m = -3.4e38f;
    for (int n = 0; n < 64; n++) m = fmaxf(m, hp[(size_t)n*256]);
    part[((size_t)b*16 + ch)*256 + o] = m;
}
__global__ void fmax_kernel(const float* __restrict__ part, float* __restrict__ out) {
    int b = blockIdx.x, o = threadIdx.x;
    float m = -3.4e38f;
    for (int c = 0; c < 16; c++) m = fmaxf(m, part[((size_t)b*16 + c)*256 + o]);
    out[(size_t)b*256 + o] = m;
}

// ---------------- host orchestration ----------------
struct Scratch {
    float *hA, *hB, *u, *w, *ymax, *ymin, *xx, *dist, *nodemin, *ps, *pq, *scale, *shift, *part;
    int* idx;
};

// side streams + events: s2 = gemm overlap, s3 = topk half-pipeline
static cudaStream_t g_s2 = nullptr, g_s3 = nullptr;
static cudaEvent_t  g_evF[4], g_evJ[4], g_evDA[4], g_evTA[4];

template<int C, int O>
static void run_layer(const float* hin, float* hout, const float* W,
                      const float* g, const float* bt, const Scratch& Z, int li) {
    int P = 262144 / O;
    // fork: gemm(hin, W) is independent of the xx->dist->topk chain
    cudaEventRecord(g_evF[li], 0);
    cudaStreamWaitEvent(g_s2, g_evF[li], 0);
    gemm_kernel<C, O><<<dim3(O/64, BN/128), 256, 0, g_s2>>>(hin, W, Z.u, Z.w);
    cudaEventRecord(g_evJ[li], g_s2);

    xx_kernel<C><<<BN/256, 256>>>(hin, Z.xx);
    // pipelined halves: topk(first 8 batches) overlaps dist(last 8 batches)
    if constexpr (C == 4) {
        dist4_kernel<<<dim3(16, 16, 8), 256>>>(hin, Z.xx, Z.dist, Z.nodemin, 0);
        cudaEventRecord(g_evDA[li], 0);
        dist4_kernel<<<dim3(16, 16, 8), 256>>>(hin, Z.xx, Z.dist, Z.nodemin, 8);
    } else {
        dist_kernel<C><<<dim3(8, 8, 8), 256>>>(hin, Z.xx, Z.dist, Z.nodemin, 0);
        cudaEventRecord(g_evDA[li], 0);
        dist_kernel<C><<<dim3(8, 8, 8), 256>>>(hin, Z.xx, Z.dist, Z.nodemin, 8);
    }
    cudaStreamWaitEvent(g_s3, g_evDA[li], 0);
    topk_kernel<<<dim3(NPTS/8, 8), 256, 0, g_s3>>>(Z.dist, Z.nodemin, Z.idx, 0);
    cudaEventRecord(g_evTA[li], g_s3);
    topk_kernel<<<dim3(NPTS/8, 8), 256>>>(Z.dist, Z.nodemin, Z.idx, 8);

    // join before the gather needs idx (both halves) and u/w
    cudaStreamWaitEvent(0, g_evTA[li], 0);
    cudaStreamWaitEvent(0, g_evJ[li], 0);
    stats_kernel<O><<<BN/64, 256>>>(Z.u, Z.w, Z.idx, Z.ps, Z.pq, Z.ymax, Z.ymin, P);
    bnstats_kernel<<<O, 128>>>(Z.ps, Z.pq, g, bt, Z.scale, Z.shift, P);
    finalize_kernel<O><<<(BN*O/4)/256, 256>>>((const float4*)Z.ymax, (const float4*)Z.ymin,
                                              (const float4*)Z.scale, (const float4*)Z.shift,
                                              (float4*)hout);
}

extern "C" void kernel_launch(void* const* d_in, const int* in_sizes, int n_in,
                              void* d_out, int out_size) {
    if (g_s2 == nullptr) {                          // one-time resource setup (first,
        cudaStreamCreateWithFlags(&g_s2, cudaStreamNonBlocking);   // uncaptured call)
        cudaStreamCreateWithFlags(&g_s3, cudaStreamNonBlocking);
        for (int i = 0; i < 4; i++) {
            cudaEventCreateWithFlags(&g_evF[i],  cudaEventDisableTiming);
            cudaEventCreateWithFlags(&g_evJ[i],  cudaEventDisableTiming);
            cudaEventCreateWithFlags(&g_evDA[i], cudaEventDisableTiming);
            cudaEventCreateWithFlags(&g_evTA[i], cudaEventDisableTiming);
        }
    }
    const float* x = (const float*)d_in[0];
    const float* Wp[4]; const float* gp[4]; const float* bp[4];
    for (int i = 0; i < 4; i++) {
        Wp[i] = (const float*)d_in[1 + 3*i];
        gp[i] = (const float*)d_in[2 + 3*i];
        bp[i] = (const float*)d_in[3 + 3*i];
    }
    Scratch Z;
    cudaGetSymbolAddress((void**)&Z.hA,      g_hA);
    cudaGetSymbolAddress((void**)&Z.hB,      g_hB);
    cudaGetSymbolAddress((void**)&Z.u,       g_u);
    cudaGetSymbolAddress((void**)&Z.w,       g_w);
    cudaGetSymbolAddress((void**)&Z.ymax,    g_ymax);
    cudaGetSymbolAddress((void**)&Z.ymin,    g_ymin);
    cudaGetSymbolAddress((void**)&Z.xx,      g_xx);
    cudaGetSymbolAddress((void**)&Z.dist,    g_dist);
    cudaGetSymbolAddress((void**)&Z.nodemin, g_nodemin);
    cudaGetSymbolAddress((void**)&Z.ps,      g_ps);
    cudaGetSymbolAddress((void**)&Z.pq,      g_pq);
    cudaGetSymbolAddress((void**)&Z.scale,   g_scale);
    cudaGetSymbolAddress((void**)&Z.shift,   g_shift);
    cudaGetSymbolAddress((void**)&Z.part,    g_part);
    cudaGetSymbolAddress((void**)&Z.idx,     g_idx);

    prep_kernel<<<(BN*4)/256, 256>>>(x, Z.hA);

    run_layer<4,   64 >(Z.hA, Z.hB, Wp[0], gp[0], bp[0], Z, 0);
    run_layer<64,  64 >(Z.hB, Z.hA, Wp[1], gp[1], bp[1], Z, 1);
    run_layer<64,  128>(Z.hA, Z.hB, Wp[2], gp[2], bp[2], Z, 2);
    run_layer<128, 256>(Z.hB, Z.hA, Wp[3], gp[3], bp[3], Z, 3);

    pmax_kernel<<<dim3(16, BATCH), 256>>>(Z.hA, Z.part);
    fmax_kernel<<<BATCH, 256>>>(Z.part, (float*)d_out);
}